// round 4
// baseline (speedup 1.0000x reference)
#include <cuda_runtime.h>

#define NPTS (512 * 512)
#define THREADS 128
#define BLOCKS 456   // 152 SMs * 3 CTAs/SM (smem-limited)

// ---- shared layout (float offsets) ----
// Cp layers 0/1: [i][k][o], k-row stride 34 floats (bank swizzle), i stride 448
#define IST 448
#define KST 34
#define OFF_CP0 0                      // 2*448  = 896
#define OFF_SB0 896                    // 2*32   = 64
#define OFF_CP1 960                    // 32*448 = 14336
#define OFF_SB1 15296                  // 32*32  = 1024
#define OFF_CP2 16320                  // [k][i], stride 33: 13*33=429 -> pad 432
#define OFF_SB2 16752                  // 32
#define SMEM_FLOATS 16784              // 67136 bytes -> 3 CTAs/SM

__device__ __forceinline__ float sigmoidf_(float x) {
    return 1.0f / (1.0f + __expf(-x));
}

// packed dual-fma: acc += a * b (elementwise on float2), via fma.rn.f32x2
__device__ __forceinline__ void ffma2(float2& acc, float2 a, float2 b) {
    asm("{\n\t"
        ".reg .b64 ra, rb, rc;\n\t"
        "mov.b64 ra, {%2,%3};\n\t"
        "mov.b64 rb, {%4,%5};\n\t"
        "mov.b64 rc, {%0,%1};\n\t"
        "fma.rn.f32x2 rc, ra, rb, rc;\n\t"
        "mov.b64 {%0,%1}, rc;\n\t"
        "}"
        : "+f"(acc.x), "+f"(acc.y)
        : "f"(a.x), "f"(a.y), "f"(b.x), "f"(b.y));
}

// uniform cubic B-spline taps at x; clamped indices k0..k3 in [0,12]
__device__ __forceinline__ void spline_taps(float x, float& b0, float& b1, float& b2, float& b3,
                                            int& k0, int& k1, int& k2, int& k3)
{
    float u = x * 10.0f;
    bool inr = (u >= -3.0f) && (u < 13.0f);
    float uc = inr ? u : 0.0f;
    float f  = floorf(uc);
    float t  = uc - f;
    int   m  = (int)f + 3;

    const float C6 = 0.16666667f;
    float t2 = t * t, t3 = t2 * t;
    float omt = 1.0f - t;
    b0 = omt * omt * omt * C6;
    b1 = (3.0f * t3 - 6.0f * t2 + 4.0f) * C6;
    b2 = ((3.0f - 3.0f * t) * t2 + 3.0f * t + 1.0f) * C6;
    b3 = t3 * C6;
    if (!inr)   { b0 = 0.0f; b1 = 0.0f; b2 = 0.0f; b3 = 0.0f; }
    if (m < 3)  b0 = 0.0f;
    if (m < 2)  b1 = 0.0f;
    if (m < 1)  b2 = 0.0f;
    if (m > 12) b3 = 0.0f;
    if (m > 13) b2 = 0.0f;
    if (m > 14) b1 = 0.0f;
    int j = m - 3;
    k0 = max(j, 0);
    k1 = max(min(j + 1, 12), 0);
    k2 = max(min(j + 2, 12), 0);
    k3 = min(j + 3, 12);
}

// wide KAN layer (OUT multiple of 8): weights [i][k][o], float2 loads + f32x2 fma
template <int IN, int OUT>
__device__ __forceinline__ void kan_layer_w(const float* xin, float* xout,
                                            const float* __restrict__ sCp,
                                            const float* __restrict__ sSb)
{
    float2 acc[OUT / 2];
#pragma unroll
    for (int o = 0; o < OUT / 2; o++) acc[o] = make_float2(0.0f, 0.0f);

#pragma unroll 1
    for (int i = 0; i < IN; i++) {
        float x = xin[i];
        float b0, b1, b2, b3; int k0, k1, k2, k3;
        spline_taps(x, b0, b1, b2, b3, k0, k1, k2, k3);
        float base = x * sigmoidf_(x);

        const float* R = sCp + i * IST;
        const float2* r0 = reinterpret_cast<const float2*>(R + k0 * KST);
        const float2* r1 = reinterpret_cast<const float2*>(R + k1 * KST);
        const float2* r2 = reinterpret_cast<const float2*>(R + k2 * KST);
        const float2* r3 = reinterpret_cast<const float2*>(R + k3 * KST);
        const float4* S4 = reinterpret_cast<const float4*>(sSb + i * OUT);

        float2 b0p = make_float2(b0, b0);
        float2 b1p = make_float2(b1, b1);
        float2 b2p = make_float2(b2, b2);
        float2 b3p = make_float2(b3, b3);
        float2 bsp = make_float2(base, base);

#pragma unroll
        for (int q = 0; q < OUT / 4; q++) {
            float4 s = S4[q];                       // uniform addr -> broadcast
            float2 c;
            c = r0[2 * q];     ffma2(acc[2 * q],     b0p, c);
            c = r0[2 * q + 1]; ffma2(acc[2 * q + 1], b0p, c);
            c = r1[2 * q];     ffma2(acc[2 * q],     b1p, c);
            c = r1[2 * q + 1]; ffma2(acc[2 * q + 1], b1p, c);
            c = r2[2 * q];     ffma2(acc[2 * q],     b2p, c);
            c = r2[2 * q + 1]; ffma2(acc[2 * q + 1], b2p, c);
            c = r3[2 * q];     ffma2(acc[2 * q],     b3p, c);
            c = r3[2 * q + 1]; ffma2(acc[2 * q + 1], b3p, c);
            ffma2(acc[2 * q],     bsp, make_float2(s.x, s.y));
            ffma2(acc[2 * q + 1], bsp, make_float2(s.z, s.w));
        }
    }
#pragma unroll
    for (int o = 0; o < OUT / 2; o++) { xout[2 * o] = acc[o].x; xout[2 * o + 1] = acc[o].y; }
}

// final layer (OUT=1): weights [k][i] stride 33 (conflict-free divergent taps)
__device__ __forceinline__ float kan_layer_1(const float* xin,
                                             const float* __restrict__ sCp,
                                             const float* __restrict__ sSb)
{
    float acc = 0.0f;
#pragma unroll 1
    for (int i = 0; i < 32; i++) {
        float x = xin[i];
        float b0, b1, b2, b3; int k0, k1, k2, k3;
        spline_taps(x, b0, b1, b2, b3, k0, k1, k2, k3);
        float base = x * sigmoidf_(x);
        acc = fmaf(sSb[i], base, acc);
        acc = fmaf(b0, sCp[k0 * 33 + i], acc);
        acc = fmaf(b1, sCp[k1 * 33 + i], acc);
        acc = fmaf(b2, sCp[k2 * 33 + i], acc);
        acc = fmaf(b3, sCp[k3 * 33 + i], acc);
    }
    return acc;
}

__global__ void __launch_bounds__(THREADS, 3)
kan_forward(const float* __restrict__ coords,
            const float* __restrict__ coef0, const float* __restrict__ sb0, const float* __restrict__ sp0,
            const float* __restrict__ coef1, const float* __restrict__ sb1, const float* __restrict__ sp1,
            const float* __restrict__ coef2, const float* __restrict__ sb2, const float* __restrict__ sp2,
            const float* __restrict__ dbias,
            float* __restrict__ out)
{
    extern __shared__ float smem[];

    // ---- stage weights: fold sp into coef, transpose to [i][k][o] (layers 0,1) ----
    // layer0: IN=2, OUT=32
    for (int idx = threadIdx.x; idx < 2 * 13 * 32; idx += THREADS) {
        int i = idx / (13 * 32), r = idx % (13 * 32), k = r / 32, o = r % 32;
        smem[OFF_CP0 + i * IST + k * KST + o] = sp0[i * 32 + o] * coef0[(i * 32 + o) * 13 + k];
    }
    // layer1: IN=32, OUT=32
    for (int idx = threadIdx.x; idx < 32 * 13 * 32; idx += THREADS) {
        int i = idx / (13 * 32), r = idx % (13 * 32), k = r / 32, o = r % 32;
        smem[OFF_CP1 + i * IST + k * KST + o] = sp1[i * 32 + o] * coef1[(i * 32 + o) * 13 + k];
    }
    // layer2: IN=32, OUT=1 -> [k][i] stride 33
    for (int idx = threadIdx.x; idx < 13 * 32; idx += THREADS) {
        int k = idx / 32, i = idx % 32;
        smem[OFF_CP2 + k * 33 + i] = sp2[i] * coef2[i * 13 + k];
    }
    for (int idx = threadIdx.x; idx < 64;   idx += THREADS) smem[OFF_SB0 + idx] = sb0[idx];
    for (int idx = threadIdx.x; idx < 1024; idx += THREADS) smem[OFF_SB1 + idx] = sb1[idx];
    for (int idx = threadIdx.x; idx < 32;   idx += THREADS) smem[OFF_SB2 + idx] = sb2[idx];
    __syncthreads();

    float bias = dbias[0];
    int stride = gridDim.x * THREADS;
    for (int p = blockIdx.x * THREADS + threadIdx.x; p < NPTS; p += stride) {
        float2 c = reinterpret_cast<const float2*>(coords)[p];
        float h0[2] = { c.x, c.y };
        float h1[32], h2[32];
        kan_layer_w<2, 32>(h0, h1, smem + OFF_CP0, smem + OFF_SB0);
        kan_layer_w<32, 32>(h1, h2, smem + OFF_CP1, smem + OFF_SB1);
        float lg = kan_layer_1(h2, smem + OFF_CP2, smem + OFF_SB2);
        out[p] = sigmoidf_(lg + bias);
    }
}

extern "C" void kernel_launch(void* const* d_in, const int* in_sizes, int n_in,
                              void* d_out, int out_size)
{
    // order: coords, grid0, coef0, sb0, sp0, grid1, coef1, sb1, sp1, grid2, coef2, sb2, sp2, density_bias
    const float* coords = (const float*)d_in[0];
    const float* coef0  = (const float*)d_in[2];
    const float* sb0    = (const float*)d_in[3];
    const float* sp0    = (const float*)d_in[4];
    const float* coef1  = (const float*)d_in[6];
    const float* sb1    = (const float*)d_in[7];
    const float* sp1    = (const float*)d_in[8];
    const float* coef2  = (const float*)d_in[10];
    const float* sb2    = (const float*)d_in[11];
    const float* sp2    = (const float*)d_in[12];
    const float* dbias  = (const float*)d_in[13];
    float* out = (float*)d_out;

    size_t smem_bytes = SMEM_FLOATS * sizeof(float);
    cudaFuncSetAttribute(kan_forward, cudaFuncAttributeMaxDynamicSharedMemorySize, (int)smem_bytes);
    kan_forward<<<BLOCKS, THREADS, smem_bytes>>>(coords,
                                                 coef0, sb0, sp0,
                                                 coef1, sb1, sp1,
                                                 coef2, sb2, sp2,
                                                 dbias, out);
}

// round 7
// speedup vs baseline: 1.3915x; 1.3915x over previous
#include <cuda_runtime.h>
#include <cuda_fp16.h>
#include <cstdint>

#define THREADS 128
#define BLOCKS  456
#define NPTS    (512 * 512)
#define NTILES  2048              // 128 points per block-tile

// ---- smem byte layout ----
#define OFF_BFRAG 0               // 32 kt x 4 nt x 2 regs x 128B = 32768
#define OFF_ABUF  32768           // 4 warps x 32 rows x 256B = 32768
#define OFF_L0CP  65536           // 832 f32 [i][o][k]
#define OFF_L0SB  68864           // 64 f32
#define OFF_L2CP  69120           // 13*33 f32 [k][col] stride 33 -> 429 f -> 1728B
#define OFF_L2SB  70848           // 32 f32
#define SMEM_BYTES 71040

// ---------------- helpers ----------------
__device__ __forceinline__ uint32_t smem_u32(const void* p) {
    uint32_t a;
    asm("{ .reg .u64 t; cvta.to.shared.u64 t, %1; cvt.u32.u64 %0, t; }" : "=r"(a) : "l"(p));
    return a;
}
__device__ __forceinline__ void sts32(uint32_t a, uint32_t v) {
    asm volatile("st.shared.b32 [%0], %1;" :: "r"(a), "r"(v) : "memory");
}
__device__ __forceinline__ void sts16(uint32_t a, uint16_t v) {
    asm volatile("st.shared.b16 [%0], %1;" :: "r"(a), "h"(v) : "memory");
}
__device__ __forceinline__ void sts128z(uint32_t a) {
    asm volatile("st.shared.v4.b32 [%0], {%1,%1,%1,%1};" :: "r"(a), "r"(0u) : "memory");
}
__device__ __forceinline__ uint32_t lds32(uint32_t a) {
    uint32_t v;
    asm volatile("ld.shared.b32 %0, [%1];" : "=r"(v) : "r"(a));
    return v;
}
__device__ __forceinline__ void ldmatrix_x4(uint32_t& r0, uint32_t& r1, uint32_t& r2, uint32_t& r3,
                                            uint32_t addr) {
    asm volatile("ldmatrix.sync.aligned.m8n8.x4.shared.b16 {%0,%1,%2,%3}, [%4];"
                 : "=r"(r0), "=r"(r1), "=r"(r2), "=r"(r3) : "r"(addr));
}
__device__ __forceinline__ void mma16816(float* d, const uint32_t* a, uint32_t b0, uint32_t b1) {
    asm volatile("mma.sync.aligned.m16n8k16.row.col.f32.f16.f16.f32 "
                 "{%0,%1,%2,%3}, {%4,%5,%6,%7}, {%8,%9}, {%0,%1,%2,%3};"
                 : "+f"(d[0]), "+f"(d[1]), "+f"(d[2]), "+f"(d[3])
                 : "r"(a[0]), "r"(a[1]), "r"(a[2]), "r"(a[3]), "r"(b0), "r"(b1));
}
__device__ __forceinline__ float sigmoidf_(float x) { return 1.0f / (1.0f + __expf(-x)); }
__device__ __forceinline__ uint32_t h2bits(float lo, float hi) {
    __half2 h = __floats2half2_rn(lo, hi);
    return *reinterpret_cast<uint32_t*>(&h);
}

// uniform cubic B-spline: 4 taps (zeroed if invalid) + interval j (j=-3 sentinel when oor)
__device__ __forceinline__ void spline4(float x, float& b0, float& b1, float& b2, float& b3, int& j)
{
    float u = x * 10.0f;
    bool inr = (u >= -3.0f) && (u < 13.0f);
    float uc = inr ? u : 0.0f;
    float f = floorf(uc);
    float t = uc - f;
    j = (int)f;
    const float C6 = 0.16666667f;
    float t2 = t * t, t3 = t2 * t;
    float omt = 1.0f - t;
    b0 = omt * omt * omt * C6;
    b1 = (3.0f * t3 - 6.0f * t2 + 4.0f) * C6;
    b2 = ((3.0f - 3.0f * t) * t2 + 3.0f * t + 1.0f) * C6;
    b3 = t3 * C6;
    if (!inr) { b0 = 0.0f; b1 = 0.0f; b2 = 0.0f; b3 = 0.0f; j = -3; }
    if (j < 0)  b0 = 0.0f;
    if (j < -1) b1 = 0.0f;
    if (j < -2) b2 = 0.0f;
    if (j > 9)  b3 = 0.0f;
    if (j > 10) b2 = 0.0f;
    if (j > 11) b1 = 0.0f;
}

__global__ void __launch_bounds__(THREADS, 3)
kan_forward(const float* __restrict__ coords,
            const float* __restrict__ coef0, const float* __restrict__ sb0, const float* __restrict__ sp0,
            const float* __restrict__ coef1, const float* __restrict__ sb1, const float* __restrict__ sp1,
            const float* __restrict__ coef2, const float* __restrict__ sb2, const float* __restrict__ sp2,
            const float* __restrict__ dbias,
            float* __restrict__ out)
{
    extern __shared__ char smem[];
    float* smf = reinterpret_cast<float*>(smem);
    const uint32_t sbase = smem_u32(smem);
    const int tid  = threadIdx.x;
    const int wid  = tid >> 5;
    const int lane = tid & 31;

    // ======== one-time staging ========
    // layer0: [i][o][k] f32, sp folded
    for (int idx = tid; idx < 832; idx += THREADS)
        smf[OFF_L0CP / 4 + idx] = sp0[idx / 13] * coef0[idx];
    for (int idx = tid; idx < 64; idx += THREADS)
        smf[OFF_L0SB / 4 + idx] = sb0[idx];
    // layer2: [k][col] stride 33 f32
    for (int idx = tid; idx < 13 * 32; idx += THREADS) {
        int k = idx / 32, i = idx % 32;
        smf[OFF_L2CP / 4 + k * 33 + i] = sp2[i] * coef2[i * 13 + k];
    }
    for (int idx = tid; idx < 32; idx += THREADS)
        smf[OFF_L2SB / 4 + idx] = sb2[idx];
    // layer1 B in mma fragment layout, fp16.
    // feature f = 16*i + r: r=0 -> silu weight sb1[i,o]; r=1..13 -> sp1*coef1[i,o,r-1]; r=14,15 -> 0
    for (int e = tid; e < 8192; e += THREADS) {
        int L = e & 31, reg = (e >> 5) & 1, nt = (e >> 6) & 3, kt = e >> 8;
        int k = kt * 16 + 2 * (L & 3) + 8 * reg;
        int n = nt * 8 + (L >> 2);
        float w[2];
#pragma unroll
        for (int z = 0; z < 2; z++) {
            int f = k + z;
            int i = f >> 4, r = f & 15;
            float v = 0.0f;
            if (r == 0)       v = sb1[i * 32 + n];
            else if (r <= 13) v = sp1[i * 32 + n] * coef1[(i * 32 + n) * 13 + (r - 1)];
            w[z] = v;
        }
        uint32_t addr = sbase + OFF_BFRAG + (uint32_t)(((kt * 4 + nt) * 2 + reg) * 128 + L * 4);
        sts32(addr, h2bits(w[0], w[1]));
    }
    __syncthreads();

    const float bias = dbias[0];
    const uint32_t ABw     = sbase + OFF_ABUF + (uint32_t)wid * 8192u;
    const uint32_t rowbase = ABw + (uint32_t)lane * 256u;
    const uint32_t swzm    = (uint32_t)(lane & 7) << 4;
    const int lrow  = lane & 15;
    const int lcolb = (lane >> 4) * 16;
    const uint32_t rmask = (uint32_t)(lrow & 7) << 4;

    for (int tile = blockIdx.x; tile < NTILES; tile += gridDim.x) {
        const int pbase = tile * 128 + wid * 32;
        const int p = pbase + lane;

        // ---- layer 0 (scalar) ----
        float2 cc = reinterpret_cast<const float2*>(coords)[p];
        float h1[32];
#pragma unroll
        for (int o = 0; o < 32; o++) h1[o] = 0.0f;
#pragma unroll
        for (int i = 0; i < 2; i++) {
            float x = (i == 0) ? cc.x : cc.y;
            float b0, b1, b2, b3; int j;
            spline4(x, b0, b1, b2, b3, j);
            int k0 = max(j, 0);
            int k1 = min(max(j + 1, 0), 12);
            int k2 = min(max(j + 2, 0), 12);
            int k3 = min(j + 3, 12);
            float base = x * sigmoidf_(x);
            const float* C = smf + OFF_L0CP / 4 + i * (32 * 13);
            const float* S = smf + OFF_L0SB / 4 + i * 32;
#pragma unroll
            for (int o = 0; o < 32; o++) {
                float a = h1[o];
                a = fmaf(S[o], base, a);
                a = fmaf(b0, C[o * 13 + k0], a);
                a = fmaf(b1, C[o * 13 + k1], a);
                a = fmaf(b2, C[o * 13 + k2], a);
                a = fmaf(b3, C[o * 13 + k3], a);
                h1[o] = a;
            }
        }

        // ---- layer 1: GEMM D[32x32] = A[32x512] * B ----
        float acc[2][4][4];
#pragma unroll
        for (int mt = 0; mt < 2; mt++)
#pragma unroll
            for (int nt = 0; nt < 4; nt++)
#pragma unroll
                for (int e = 0; e < 4; e++) acc[mt][nt][e] = 0.0f;

#pragma unroll 1
        for (int c = 0; c < 4; c++) {
            // zero my 256B A row (chunk-group swizzled)
#pragma unroll
            for (int q = 0; q < 16; q++)
                sts128z(rowbase + (((uint32_t)q * 16u) ^ swzm));

            // scatter features for inputs 8c..8c+7
#pragma unroll
            for (int il = 0; il < 8; il++) {
                float x = h1[c * 8 + il];
                float b0, b1, b2, b3; int j;
                spline4(x, b0, b1, b2, b3, j);
                float base = x * sigmoidf_(x);
                uint32_t u01 = h2bits(b0, b1);
                uint32_t u23 = h2bits(b2, b3);
                int s1 = 1 + j;               // slot of first tap, in [-2, 13]
                int wi = s1 >> 1;             // word of first tap, in [-1, 6]
                bool odd = (s1 & 1) != 0;
                uint32_t v1 = odd ? (u01 << 16) : u01;
                uint32_t v2 = odd ? ((u01 >> 16) | (u23 << 16)) : u23;
                uint32_t v3 = odd ? (u23 >> 16) : 0u;
                uint32_t bb = (uint32_t)(32 * il);
                if (wi >= 0) sts32(rowbase + ((bb + 4u * (uint32_t)wi) ^ swzm), v1);
                sts32(rowbase + ((bb + 4u * (uint32_t)(wi + 1)) ^ swzm), v2);
                if (wi <= 5) sts32(rowbase + ((bb + 4u * (uint32_t)(wi + 2)) ^ swzm), v3);
                // silu at slot 0 (store after taps; overwrites only a zeroed b0 when s1==0)
                __half hs = __float2half_rn(base);
                sts16(rowbase + (bb ^ swzm), __half_as_ushort(hs));
            }
            __syncwarp();

            // 8 k-tiles of k=16 in this chunk
#pragma unroll
            for (int kt = 0; kt < 8; kt++) {
                uint32_t a0[4], a1[4];
                uint32_t inrow = ((uint32_t)(kt * 32 + lcolb)) ^ rmask;
                ldmatrix_x4(a0[0], a0[1], a0[2], a0[3], ABw + (uint32_t)lrow * 256u + inrow);
                ldmatrix_x4(a1[0], a1[1], a1[2], a1[3], ABw + (uint32_t)(16 + lrow) * 256u + inrow);
                int ktg = c * 8 + kt;
#pragma unroll
                for (int nt = 0; nt < 4; nt++) {
                    uint32_t baddr = sbase + OFF_BFRAG
                                   + (uint32_t)(((ktg * 4 + nt) * 2) * 128 + lane * 4);
                    uint32_t b0 = lds32(baddr);
                    uint32_t b1 = lds32(baddr + 128u);
                    mma16816(acc[0][nt], a0, b0, b1);
                    mma16816(acc[1][nt], a1, b0, b1);
                }
            }
            __syncwarp();
        }

        // ---- layer 2 in fragment space ----
        // value (mt, nt, e): row = 16*mt + 8*(e>>1) + lane/4 ; col = 8*nt + 2*(lane&3) + (e&1)
        const float* C2 = smf + OFF_L2CP / 4;
        const float* S2 = smf + OFF_L2SB / 4;
        float ps[4] = {0.0f, 0.0f, 0.0f, 0.0f};
#pragma unroll
        for (int mt = 0; mt < 2; mt++)
#pragma unroll
            for (int nt = 0; nt < 4; nt++)
#pragma unroll
                for (int e = 0; e < 4; e++) {
                    float x = acc[mt][nt][e];
                    int col = nt * 8 + 2 * (lane & 3) + (e & 1);
                    float b0, b1, b2, b3; int j;
                    spline4(x, b0, b1, b2, b3, j);
                    int k0 = max(j, 0);
                    int k1 = min(max(j + 1, 0), 12);
                    int k2 = min(max(j + 2, 0), 12);
                    int k3 = min(j + 3, 12);
                    float g = S2[col] * (x * sigmoidf_(x));
                    g = fmaf(b0, C2[k0 * 33 + col], g);
                    g = fmaf(b1, C2[k1 * 33 + col], g);
                    g = fmaf(b2, C2[k2 * 33 + col], g);
                    g = fmaf(b3, C2[k3 * 33 + col], g);
                    ps[mt * 2 + (e >> 1)] += g;
                }
        // reduce over the 4-lane quad (cols)
#pragma unroll
        for (int s = 0; s < 4; s++) {
            ps[s] += __shfl_xor_sync(0xffffffffu, ps[s], 1);
            ps[s] += __shfl_xor_sync(0xffffffffu, ps[s], 2);
        }
        if ((lane & 3) == 0) {
#pragma unroll
            for (int s = 0; s < 4; s++) {
                int row = 16 * (s >> 1) + 8 * (s & 1) + (lane >> 2);
                out[pbase + row] = sigmoidf_(ps[s] + bias);
            }
        }
    }
}

extern "C" void kernel_launch(void* const* d_in, const int* in_sizes, int n_in,
                              void* d_out, int out_size)
{
    // order: coords, grid0, coef0, sb0, sp0, grid1, coef1, sb1, sp1, grid2, coef2, sb2, sp2, density_bias
    const float* coords = (const float*)d_in[0];
    const float* coef0  = (const float*)d_in[2];
    const float* sb0    = (const float*)d_in[3];
    const float* sp0    = (const float*)d_in[4];
    const float* coef1  = (const float*)d_in[6];
    const float* sb1    = (const float*)d_in[7];
    const float* sp1    = (const float*)d_in[8];
    const float* coef2  = (const float*)d_in[10];
    const float* sb2    = (const float*)d_in[11];
    const float* sp2    = (const float*)d_in[12];
    const float* dbias  = (const float*)d_in[13];
    float* out = (float*)d_out;

    cudaFuncSetAttribute(kan_forward, cudaFuncAttributeMaxDynamicSharedMemorySize, SMEM_BYTES);
    kan_forward<<<BLOCKS, THREADS, SMEM_BYTES>>>(coords,
                                                 coef0, sb0, sp0,
                                                 coef1, sb1, sp1,
                                                 coef2, sb2, sp2,
                                                 dbias, out);
}

// round 8
// speedup vs baseline: 1.4992x; 1.0774x over previous
#include <cuda_runtime.h>
#include <cuda_fp16.h>
#include <cstdint>

#define THREADS 128
#define BLOCKS  592               // 148 SMs * 4 CTAs
#define NPTS    (512 * 512)
#define NTILES  2048              // 128 points per block-tile

// ---- smem byte layout ----
#define OFF_BFRAG 0               // 32 kt x 4 nt x 256B (reg-interleaved) = 32768
#define OFF_ABUF  32768           // 4 warps x 32 rows x 128B = 16384
#define OFF_L0CP  49152           // 832 f32 [i][o][k] = 3328
#define OFF_L0SB  52480           // 64 f32
#define OFF_L2CP  52736           // 13*33 f32 stride 33 -> 1728B
#define OFF_L2SB  54464           // 32 f32
#define SMEM_BYTES 54592          // x4 CTAs = 218368 <= SM smem

// ---------------- helpers ----------------
__device__ __forceinline__ uint32_t smem_u32(const void* p) {
    uint32_t a;
    asm("{ .reg .u64 t; cvta.to.shared.u64 t, %1; cvt.u32.u64 %0, t; }" : "=r"(a) : "l"(p));
    return a;
}
__device__ __forceinline__ void sts32(uint32_t a, uint32_t v) {
    asm volatile("st.shared.b32 [%0], %1;" :: "r"(a), "r"(v) : "memory");
}
__device__ __forceinline__ void sts16(uint32_t a, uint16_t v) {
    asm volatile("st.shared.b16 [%0], %1;" :: "r"(a), "h"(v) : "memory");
}
__device__ __forceinline__ void sts128z(uint32_t a) {
    asm volatile("st.shared.v4.b32 [%0], {%1,%1,%1,%1};" :: "r"(a), "r"(0u) : "memory");
}
__device__ __forceinline__ void lds64(uint32_t& v0, uint32_t& v1, uint32_t a) {
    asm volatile("ld.shared.v2.b32 {%0,%1}, [%2];" : "=r"(v0), "=r"(v1) : "r"(a));
}
__device__ __forceinline__ void ldmatrix_x4(uint32_t& r0, uint32_t& r1, uint32_t& r2, uint32_t& r3,
                                            uint32_t addr) {
    asm volatile("ldmatrix.sync.aligned.m8n8.x4.shared.b16 {%0,%1,%2,%3}, [%4];"
                 : "=r"(r0), "=r"(r1), "=r"(r2), "=r"(r3) : "r"(addr));
}
__device__ __forceinline__ void mma16816(float* d, const uint32_t* a, uint32_t b0, uint32_t b1) {
    asm volatile("mma.sync.aligned.m16n8k16.row.col.f32.f16.f16.f32 "
                 "{%0,%1,%2,%3}, {%4,%5,%6,%7}, {%8,%9}, {%0,%1,%2,%3};"
                 : "+f"(d[0]), "+f"(d[1]), "+f"(d[2]), "+f"(d[3])
                 : "r"(a[0]), "r"(a[1]), "r"(a[2]), "r"(a[3]), "r"(b0), "r"(b1));
}
__device__ __forceinline__ float sigmoidf_(float x) { return 1.0f / (1.0f + __expf(-x)); }
__device__ __forceinline__ uint32_t h2bits(float lo, float hi) {
    __half2 h = __floats2half2_rn(lo, hi);
    return *reinterpret_cast<uint32_t*>(&h);
}

// full-guard uniform cubic B-spline (for layer-1/2 activations, any range)
__device__ __forceinline__ void spline4(float x, float& b0, float& b1, float& b2, float& b3, int& j)
{
    float u = x * 10.0f;
    bool inr = (u >= -3.0f) && (u < 13.0f);
    float uc = inr ? u : 0.0f;
    float f = floorf(uc);
    float t = uc - f;
    j = (int)f;
    const float C6 = 0.16666667f;
    float t2 = t * t, t3 = t2 * t;
    float omt = 1.0f - t;
    b0 = omt * omt * omt * C6;
    b1 = (3.0f * t3 - 6.0f * t2 + 4.0f) * C6;
    b2 = ((3.0f - 3.0f * t) * t2 + 3.0f * t + 1.0f) * C6;
    b3 = t3 * C6;
    if (!inr) { b0 = 0.0f; b1 = 0.0f; b2 = 0.0f; b3 = 0.0f; j = -3; }
    if (j < 0)  b0 = 0.0f;
    if (j < -1) b1 = 0.0f;
    if (j < -2) b2 = 0.0f;
    if (j > 9)  b3 = 0.0f;
    if (j > 10) b2 = 0.0f;
    if (j > 11) b1 = 0.0f;
}

__global__ void __launch_bounds__(THREADS, 4)
kan_forward(const float* __restrict__ coords,
            const float* __restrict__ coef0, const float* __restrict__ sb0, const float* __restrict__ sp0,
            const float* __restrict__ coef1, const float* __restrict__ sb1, const float* __restrict__ sp1,
            const float* __restrict__ coef2, const float* __restrict__ sb2, const float* __restrict__ sp2,
            const float* __restrict__ dbias,
            float* __restrict__ out)
{
    extern __shared__ char smem[];
    float* smf = reinterpret_cast<float*>(smem);
    const uint32_t sbase = smem_u32(smem);
    const int tid  = threadIdx.x;
    const int wid  = tid >> 5;
    const int lane = tid & 31;

    // ======== one-time staging ========
    for (int idx = tid; idx < 832; idx += THREADS)
        smf[OFF_L0CP / 4 + idx] = sp0[idx / 13] * coef0[idx];
    for (int idx = tid; idx < 64; idx += THREADS)
        smf[OFF_L0SB / 4 + idx] = sb0[idx];
    for (int idx = tid; idx < 13 * 32; idx += THREADS) {
        int k = idx / 32, i = idx % 32;
        smf[OFF_L2CP / 4 + k * 33 + i] = sp2[i] * coef2[i * 13 + k];
    }
    for (int idx = tid; idx < 32; idx += THREADS)
        smf[OFF_L2SB / 4 + idx] = sb2[idx];
    // layer1 B in mma fragment layout, fp16, reg-interleaved (lane*8 + reg*4)
    for (int e = tid; e < 8192; e += THREADS) {
        int L = e & 31, reg = (e >> 5) & 1, nt = (e >> 6) & 3, kt = e >> 8;
        int k = kt * 16 + 2 * (L & 3) + 8 * reg;
        int n = nt * 8 + (L >> 2);
        float w[2];
#pragma unroll
        for (int z = 0; z < 2; z++) {
            int f = k + z;
            int i = f >> 4, r = f & 15;
            float v = 0.0f;
            if (r == 0)       v = sb1[i * 32 + n];
            else if (r <= 13) v = sp1[i * 32 + n] * coef1[(i * 32 + n) * 13 + (r - 1)];
            w[z] = v;
        }
        uint32_t addr = sbase + OFF_BFRAG + (uint32_t)((kt * 4 + nt) * 256 + L * 8 + reg * 4);
        sts32(addr, h2bits(w[0], w[1]));
    }
    __syncthreads();

    const float bias = dbias[0];
    const uint32_t ABw     = sbase + OFF_ABUF + (uint32_t)wid * 4096u;
    const uint32_t rowbase = ABw + (uint32_t)lane * 128u;
    const uint32_t swzm    = (uint32_t)(lane & 7) << 4;
    const int lrow  = lane & 15;
    const int lcolb = (lane >> 4) * 16;
    const uint32_t rmask = (uint32_t)(lrow & 7) << 4;
    const uint32_t lmA0 = ABw + (uint32_t)lrow * 128u;
    const uint32_t lmA1 = ABw + (uint32_t)(16 + lrow) * 128u;

    for (int tile = blockIdx.x; tile < NTILES; tile += gridDim.x) {
        const int pbase = tile * 128 + wid * 32;
        const int p = pbase + lane;

        // ---- layer 0 (scalar; coords in [0,1) -> no range guards) ----
        float2 cc = reinterpret_cast<const float2*>(coords)[p];
        float h1[32];
#pragma unroll
        for (int o = 0; o < 32; o++) h1[o] = 0.0f;
#pragma unroll
        for (int i = 0; i < 2; i++) {
            float x = (i == 0) ? cc.x : cc.y;
            float u = x * 10.0f;
            float fl = floorf(u);
            float t = u - fl;
            int j = (int)fl;                 // 0..9
            const float C6 = 0.16666667f;
            float t2 = t * t, t3 = t2 * t;
            float omt = 1.0f - t;
            float b0 = omt * omt * omt * C6;
            float b1 = (3.0f * t3 - 6.0f * t2 + 4.0f) * C6;
            float b2 = ((3.0f - 3.0f * t) * t2 + 3.0f * t + 1.0f) * C6;
            float b3 = t3 * C6;
            float base = x * sigmoidf_(x);
            const float* C = smf + OFF_L0CP / 4 + i * (32 * 13) + j;
            const float* S = smf + OFF_L0SB / 4 + i * 32;
#pragma unroll
            for (int o = 0; o < 32; o++) {
                float a = h1[o];
                a = fmaf(S[o], base, a);
                a = fmaf(b0, C[o * 13 + 0], a);
                a = fmaf(b1, C[o * 13 + 1], a);
                a = fmaf(b2, C[o * 13 + 2], a);
                a = fmaf(b3, C[o * 13 + 3], a);
                h1[o] = a;
            }
        }

        // ---- layer 1: GEMM D[32x32] = A[32x512] * B, 8 chunks of 64 features ----
        float acc[2][4][4];
#pragma unroll
        for (int mt = 0; mt < 2; mt++)
#pragma unroll
            for (int nt = 0; nt < 4; nt++)
#pragma unroll
                for (int e = 0; e < 4; e++) acc[mt][nt][e] = 0.0f;

#pragma unroll 1
        for (int c = 0; c < 8; c++) {
            // zero my 128B A row
#pragma unroll
            for (int q = 0; q < 8; q++)
                sts128z(rowbase + (((uint32_t)q * 16u) ^ swzm));

            // scatter features for inputs 4c..4c+3
#pragma unroll
            for (int il = 0; il < 4; il++) {
                float x = h1[c * 4 + il];
                float b0, b1, b2, b3; int j;
                spline4(x, b0, b1, b2, b3, j);
                float base = x * sigmoidf_(x);
                uint32_t u01 = h2bits(b0, b1);
                uint32_t u23 = h2bits(b2, b3);
                int s1 = 1 + j;               // slot of first tap, in [-2, 13]
                int wi = s1 >> 1;             // word of first tap, in [-1, 6]
                bool odd = (s1 & 1) != 0;
                uint32_t v1 = odd ? (u01 << 16) : u01;
                uint32_t v2 = odd ? ((u01 >> 16) | (u23 << 16)) : u23;
                uint32_t v3 = odd ? (u23 >> 16) : 0u;
                uint32_t bb = (uint32_t)(32 * il);
                if (wi >= 0) sts32(rowbase + ((bb + 4u * (uint32_t)wi) ^ swzm), v1);
                sts32(rowbase + ((bb + 4u * (uint32_t)(wi + 1)) ^ swzm), v2);
                if (wi <= 5) sts32(rowbase + ((bb + 4u * (uint32_t)(wi + 2)) ^ swzm), v3);
                __half hs = __float2half_rn(base);
                sts16(rowbase + (bb ^ swzm), __half_as_ushort(hs));
            }
            __syncwarp();

            // 4 k-tiles of k=16 in this chunk
#pragma unroll
            for (int kt = 0; kt < 4; kt++) {
                uint32_t a0[4], a1[4];
                uint32_t inrow = ((uint32_t)(kt * 32 + lcolb)) ^ rmask;
                ldmatrix_x4(a0[0], a0[1], a0[2], a0[3], lmA0 + inrow);
                ldmatrix_x4(a1[0], a1[1], a1[2], a1[3], lmA1 + inrow);
                int ktg = c * 4 + kt;
#pragma unroll
                for (int nt = 0; nt < 4; nt++) {
                    uint32_t b0, b1;
                    lds64(b0, b1, sbase + OFF_BFRAG
                                  + (uint32_t)((ktg * 4 + nt) * 256 + lane * 8));
                    mma16816(acc[0][nt], a0, b0, b1);
                    mma16816(acc[1][nt], a1, b0, b1);
                }
            }
            __syncwarp();
        }

        // ---- layer 2 in fragment space ----
        const float* C2 = smf + OFF_L2CP / 4;
        const float* S2 = smf + OFF_L2SB / 4;
        float ps[4] = {0.0f, 0.0f, 0.0f, 0.0f};
#pragma unroll
        for (int mt = 0; mt < 2; mt++)
#pragma unroll
            for (int nt = 0; nt < 4; nt++)
#pragma unroll
                for (int e = 0; e < 4; e++) {
                    float x = acc[mt][nt][e];
                    int col = nt * 8 + 2 * (lane & 3) + (e & 1);
                    float b0, b1, b2, b3; int j;
                    spline4(x, b0, b1, b2, b3, j);
                    int k0 = max(j, 0);
                    int k1 = min(max(j + 1, 0), 12);
                    int k2 = min(max(j + 2, 0), 12);
                    int k3 = min(j + 3, 12);
                    float g = S2[col] * (x * sigmoidf_(x));
                    g = fmaf(b0, C2[k0 * 33 + col], g);
                    g = fmaf(b1, C2[k1 * 33 + col], g);
                    g = fmaf(b2, C2[k2 * 33 + col], g);
                    g = fmaf(b3, C2[k3 * 33 + col], g);
                    ps[mt * 2 + (e >> 1)] += g;
                }
#pragma unroll
        for (int s = 0; s < 4; s++) {
            ps[s] += __shfl_xor_sync(0xffffffffu, ps[s], 1);
            ps[s] += __shfl_xor_sync(0xffffffffu, ps[s], 2);
        }
        if ((lane & 3) == 0) {
#pragma unroll
            for (int s = 0; s < 4; s++) {
                int row = 16 * (s >> 1) + 8 * (s & 1) + (lane >> 2);
                out[pbase + row] = sigmoidf_(ps[s] + bias);
            }
        }
    }
}

extern "C" void kernel_launch(void* const* d_in, const int* in_sizes, int n_in,
                              void* d_out, int out_size)
{
    // order: coords, grid0, coef0, sb0, sp0, grid1, coef1, sb1, sp1, grid2, coef2, sb2, sp2, density_bias
    const float* coords = (const float*)d_in[0];
    const float* coef0  = (const float*)d_in[2];
    const float* sb0    = (const float*)d_in[3];
    const float* sp0    = (const float*)d_in[4];
    const float* coef1  = (const float*)d_in[6];
    const float* sb1    = (const float*)d_in[7];
    const float* sp1    = (const float*)d_in[8];
    const float* coef2  = (const float*)d_in[10];
    const float* sb2    = (const float*)d_in[11];
    const float* sp2    = (const float*)d_in[12];
    const float* dbias  = (const float*)d_in[13];
    float* out = (float*)d_out;

    cudaFuncSetAttribute(kan_forward, cudaFuncAttributeMaxDynamicSharedMemorySize, SMEM_BYTES);
    kan_forward<<<BLOCKS, THREADS, SMEM_BYTES>>>(coords,
                                                 coef0, sb0, sp0,
                                                 coef1, sb1, sp1,
                                                 coef2, sb2, sp2,
                                                 dbias, out);
}

// round 9
// speedup vs baseline: 1.7579x; 1.1725x over previous
#include <cuda_runtime.h>
#include <cuda_fp16.h>
#include <cstdint>

#define THREADS 128
#define BLOCKS  592               // 148 SMs * 4 CTAs
#define NPTS    (512 * 512)
#define NTILES  2048              // 128 points per block-tile

// ---- smem byte layout ----
#define OFF_BFRAG 0               // 32 kt x 4 nt x 256B (reg-interleaved) = 32768
#define OFF_ABUF  32768           // 4 warps x 32 rows x 128B = 16384
#define OFF_L0    49152           // 2 x 14 rows x 34 floats = 952 f = 3808B (row13 = sb0)
#define OFF_L2    52960           // 23 rows x 33 floats = 759 f = 3036B (zero-padded ext)
#define OFF_L2SB  55996           // 32 f = 128B
#define SMEM_BYTES 56128          // x4 CTAs = 224512 <= 228KB

// ---------------- helpers ----------------
__device__ __forceinline__ uint32_t smem_u32(const void* p) {
    uint32_t a;
    asm("{ .reg .u64 t; cvta.to.shared.u64 t, %1; cvt.u32.u64 %0, t; }" : "=r"(a) : "l"(p));
    return a;
}
__device__ __forceinline__ void sts32(uint32_t a, uint32_t v) {
    asm volatile("st.shared.b32 [%0], %1;" :: "r"(a), "r"(v) : "memory");
}
__device__ __forceinline__ void sts16(uint32_t a, uint16_t v) {
    asm volatile("st.shared.b16 [%0], %1;" :: "r"(a), "h"(v) : "memory");
}
__device__ __forceinline__ void sts128z(uint32_t a) {
    asm volatile("st.shared.v4.b32 [%0], {%1,%1,%1,%1};" :: "r"(a), "r"(0u) : "memory");
}
__device__ __forceinline__ void lds64(uint32_t& v0, uint32_t& v1, uint32_t a) {
    asm volatile("ld.shared.v2.b32 {%0,%1}, [%2];" : "=r"(v0), "=r"(v1) : "r"(a));
}
__device__ __forceinline__ void ldmatrix_x4(uint32_t& r0, uint32_t& r1, uint32_t& r2, uint32_t& r3,
                                            uint32_t addr) {
    asm volatile("ldmatrix.sync.aligned.m8n8.x4.shared.b16 {%0,%1,%2,%3}, [%4];"
                 : "=r"(r0), "=r"(r1), "=r"(r2), "=r"(r3) : "r"(addr));
}
__device__ __forceinline__ void mma16816(float* d, const uint32_t* a, uint32_t b0, uint32_t b1) {
    asm volatile("mma.sync.aligned.m16n8k16.row.col.f32.f16.f16.f32 "
                 "{%0,%1,%2,%3}, {%4,%5,%6,%7}, {%8,%9}, {%0,%1,%2,%3};"
                 : "+f"(d[0]), "+f"(d[1]), "+f"(d[2]), "+f"(d[3])
                 : "r"(a[0]), "r"(a[1]), "r"(a[2]), "r"(a[3]), "r"(b0), "r"(b1));
}
// packed dual-fma: acc += s * c (s broadcast scalar), via fma.rn.f32x2
__device__ __forceinline__ void ffma2(float2& acc, float s, float2 c) {
    asm("{\n\t"
        ".reg .b64 ra, rb, rc;\n\t"
        "mov.b64 ra, {%2,%2};\n\t"
        "mov.b64 rb, {%3,%4};\n\t"
        "mov.b64 rc, {%0,%1};\n\t"
        "fma.rn.f32x2 rc, ra, rb, rc;\n\t"
        "mov.b64 {%0,%1}, rc;\n\t"
        "}"
        : "+f"(acc.x), "+f"(acc.y)
        : "f"(s), "f"(c.x), "f"(c.y));
}
__device__ __forceinline__ float sigmoidf_(float x) { return 1.0f / (1.0f + __expf(-x)); }
__device__ __forceinline__ uint32_t h2bits(float lo, float hi) {
    __half2 h = __floats2half2_rn(lo, hi);
    return *reinterpret_cast<uint32_t*>(&h);
}

// raw uniform cubic B-spline polys (no tap zeroing); oor -> j=-3, t=0
__device__ __forceinline__ void spline_raw(float x, float& b0, float& b1, float& b2, float& b3,
                                           int& j)
{
    float u = x * 10.0f;
    bool inr = (u >= -3.0f) && (u < 13.0f);
    float uc = inr ? u : 0.0f;
    float f = floorf(uc);
    float t = uc - f;
    j = inr ? (int)f : -3;
    if (!inr) t = 0.0f;
    const float C6 = 0.16666667f;
    float t2 = t * t, t3 = t2 * t;
    float omt = 1.0f - t;
    b0 = omt * omt * omt * C6;
    b1 = (3.0f * t3 - 6.0f * t2 + 4.0f) * C6;
    b2 = ((3.0f - 3.0f * t) * t2 + 3.0f * t + 1.0f) * C6;
    b3 = t3 * C6;
}

__global__ void __launch_bounds__(THREADS, 4)
kan_forward(const float* __restrict__ coords,
            const float* __restrict__ coef0, const float* __restrict__ sb0, const float* __restrict__ sp0,
            const float* __restrict__ coef1, const float* __restrict__ sb1, const float* __restrict__ sp1,
            const float* __restrict__ coef2, const float* __restrict__ sb2, const float* __restrict__ sp2,
            const float* __restrict__ dbias,
            float* __restrict__ out)
{
    extern __shared__ char smem[];
    float* smf = reinterpret_cast<float*>(smem);
    const uint32_t sbase = smem_u32(smem);
    const int tid  = threadIdx.x;
    const int wid  = tid >> 5;
    const int lane = tid & 31;

    // ======== one-time staging ========
    // layer0 table: [i][row][o2], row 0..12 = taps (sp folded), row 13 = sb0; stride 34
    for (int idx = tid; idx < 952; idx += THREADS) {
        int i = idx / 476, r = idx % 476, k = r / 34, o = r % 34;
        float v = 0.0f;
        if (o < 32) {
            if (k < 13)      v = sp0[i * 32 + o] * coef0[(i * 32 + o) * 13 + k];
            else             v = sb0[i * 32 + o];
        }
        smf[OFF_L0 / 4 + idx] = v;
    }
    // layer2 extended table: rows 0..22, stride 33; rows 3..15 = C2[k=row-3], else 0
    for (int idx = tid; idx < 759; idx += THREADS) {
        int r = idx / 33, i = idx % 33;
        float v = 0.0f;
        int k = r - 3;
        if (i < 32 && k >= 0 && k <= 12) v = sp2[i] * coef2[i * 13 + k];
        smf[OFF_L2 / 4 + idx] = v;
    }
    for (int idx = tid; idx < 32; idx += THREADS)
        smf[OFF_L2SB / 4 + idx] = sb2[idx];
    // layer1 B in mma fragment layout, fp16, reg-interleaved (lane*8 + reg*4)
    for (int e = tid; e < 8192; e += THREADS) {
        int L = e & 31, reg = (e >> 5) & 1, nt = (e >> 6) & 3, kt = e >> 8;
        int k = kt * 16 + 2 * (L & 3) + 8 * reg;
        int n = nt * 8 + (L >> 2);
        float w[2];
#pragma unroll
        for (int z = 0; z < 2; z++) {
            int f = k + z;
            int i = f >> 4, r = f & 15;
            float v = 0.0f;
            if (r == 0)       v = sb1[i * 32 + n];
            else if (r <= 13) v = sp1[i * 32 + n] * coef1[(i * 32 + n) * 13 + (r - 1)];
            w[z] = v;
        }
        uint32_t addr = sbase + OFF_BFRAG + (uint32_t)((kt * 4 + nt) * 256 + L * 8 + reg * 4);
        sts32(addr, h2bits(w[0], w[1]));
    }
    __syncthreads();

    const float bias = dbias[0];
    const uint32_t ABw     = sbase + OFF_ABUF + (uint32_t)wid * 4096u;
    const uint32_t rowbase = ABw + (uint32_t)lane * 128u;
    const uint32_t swzm    = (uint32_t)(lane & 7) << 4;
    const int lrow  = lane & 15;
    const int lcolb = (lane >> 4) * 16;
    const uint32_t rmask = (uint32_t)(lrow & 7) << 4;
    const uint32_t lmA0 = ABw + (uint32_t)lrow * 128u;
    const uint32_t lmA1 = ABw + (uint32_t)(16 + lrow) * 128u;

    for (int tile = blockIdx.x; tile < NTILES; tile += gridDim.x) {
        const int pbase = tile * 128 + wid * 32;
        const int p = pbase + lane;

        // ---- layer 0 (float2 table + f32x2 fma; coords in [0,1) -> j in 0..9) ----
        float2 cc = reinterpret_cast<const float2*>(coords)[p];
        float2 h1p[16];
#pragma unroll
        for (int q = 0; q < 16; q++) h1p[q] = make_float2(0.0f, 0.0f);
#pragma unroll
        for (int i = 0; i < 2; i++) {
            float x = (i == 0) ? cc.x : cc.y;
            float u = x * 10.0f;
            float fl = floorf(u);
            float t = u - fl;
            int j = (int)fl;                 // 0..9
            const float C6 = 0.16666667f;
            float t2 = t * t, t3 = t2 * t;
            float omt = 1.0f - t;
            float b0 = omt * omt * omt * C6;
            float b1 = (3.0f * t3 - 6.0f * t2 + 4.0f) * C6;
            float b2 = ((3.0f - 3.0f * t) * t2 + 3.0f * t + 1.0f) * C6;
            float b3 = t3 * C6;
            float base = x * sigmoidf_(x);
            const float2* T0 = reinterpret_cast<const float2*>(smf + OFF_L0 / 4 + i * 476 + j * 34);
            const float2* T1 = reinterpret_cast<const float2*>(smf + OFF_L0 / 4 + i * 476 + (j + 1) * 34);
            const float2* T2 = reinterpret_cast<const float2*>(smf + OFF_L0 / 4 + i * 476 + (j + 2) * 34);
            const float2* T3 = reinterpret_cast<const float2*>(smf + OFF_L0 / 4 + i * 476 + (j + 3) * 34);
            const float2* TS = reinterpret_cast<const float2*>(smf + OFF_L0 / 4 + i * 476 + 13 * 34);
#pragma unroll
            for (int q = 0; q < 16; q++) {
                ffma2(h1p[q], base, TS[q]);
                ffma2(h1p[q], b0, T0[q]);
                ffma2(h1p[q], b1, T1[q]);
                ffma2(h1p[q], b2, T2[q]);
                ffma2(h1p[q], b3, T3[q]);
            }
        }
        const float* h1 = reinterpret_cast<const float*>(h1p);

        // ---- layer 1: GEMM D[32x32] = A[32x512] * B, 8 chunks of 64 features ----
        float acc[2][4][4];
#pragma unroll
        for (int mt = 0; mt < 2; mt++)
#pragma unroll
            for (int nt = 0; nt < 4; nt++)
#pragma unroll
                for (int e = 0; e < 4; e++) acc[mt][nt][e] = 0.0f;

#pragma unroll 1
        for (int c = 0; c < 8; c++) {
            // zero my 128B A row
#pragma unroll
            for (int q = 0; q < 8; q++)
                sts128z(rowbase + (((uint32_t)q * 16u) ^ swzm));

            // scatter features for inputs 4c..4c+3 (guard-free raw spline:
            // invalid taps are absorbed by wi store-guards, dummy slots 14/15,
            // or slot 0 which silu overwrites last)
#pragma unroll
            for (int il = 0; il < 4; il++) {
                float x = h1[c * 4 + il];
                float b0, b1, b2, b3; int j;
                spline_raw(x, b0, b1, b2, b3, j);
                float base = x * sigmoidf_(x);
                uint32_t u01 = h2bits(b0, b1);
                uint32_t u23 = h2bits(b2, b3);
                int s1 = 1 + j;               // slot of first tap, in [-2, 13]
                int wi = s1 >> 1;             // word of first tap, in [-1, 6]
                bool odd = (s1 & 1) != 0;
                uint32_t v1 = odd ? (u01 << 16) : u01;
                uint32_t v2 = odd ? ((u01 >> 16) | (u23 << 16)) : u23;
                uint32_t v3 = odd ? (u23 >> 16) : 0u;
                uint32_t bb = (uint32_t)(32 * il);
                if (wi >= 0) sts32(rowbase + ((bb + 4u * (uint32_t)wi) ^ swzm), v1);
                sts32(rowbase + ((bb + 4u * (uint32_t)(wi + 1)) ^ swzm), v2);
                if (wi <= 5) sts32(rowbase + ((bb + 4u * (uint32_t)(wi + 2)) ^ swzm), v3);
                __half hs = __float2half_rn(base);
                sts16(rowbase + (bb ^ swzm), __half_as_ushort(hs));
            }
            __syncwarp();

            // 4 k-tiles of k=16 in this chunk
#pragma unroll
            for (int kt = 0; kt < 4; kt++) {
                uint32_t a0[4], a1[4];
                uint32_t inrow = ((uint32_t)(kt * 32 + lcolb)) ^ rmask;
                ldmatrix_x4(a0[0], a0[1], a0[2], a0[3], lmA0 + inrow);
                ldmatrix_x4(a1[0], a1[1], a1[2], a1[3], lmA1 + inrow);
                int ktg = c * 4 + kt;
#pragma unroll
                for (int nt = 0; nt < 4; nt++) {
                    uint32_t b0, b1;
                    lds64(b0, b1, sbase + OFF_BFRAG
                                  + (uint32_t)((ktg * 4 + nt) * 256 + lane * 8));
                    mma16816(acc[0][nt], a0, b0, b1);
                    mma16816(acc[1][nt], a1, b0, b1);
                }
            }
            __syncwarp();
        }

        // ---- layer 2 in fragment space (extended zero-padded table, no clamps) ----
        const float* C2 = smf + OFF_L2 / 4;
        const float* S2 = smf + OFF_L2SB / 4;
        float ps[4] = {0.0f, 0.0f, 0.0f, 0.0f};
#pragma unroll
        for (int mt = 0; mt < 2; mt++)
#pragma unroll
            for (int nt = 0; nt < 4; nt++)
#pragma unroll
                for (int e = 0; e < 4; e++) {
                    float x = acc[mt][nt][e];
                    int col = nt * 8 + 2 * (lane & 3) + (e & 1);
                    float u = x * 10.0f;
                    bool inr = (u >= -3.0f) && (u < 13.0f);
                    float uc = inr ? u : 0.0f;
                    float fl = floorf(uc);
                    float t = uc - fl;
                    int row = inr ? ((int)fl + 3) : 19;   // rows row..row+3 in [0,22]
                    const float C6 = 0.16666667f;
                    float t2 = t * t, t3 = t2 * t;
                    float omt = 1.0f - t;
                    float b0 = omt * omt * omt * C6;
                    float b1 = (3.0f * t3 - 6.0f * t2 + 4.0f) * C6;
                    float b2 = ((3.0f - 3.0f * t) * t2 + 3.0f * t + 1.0f) * C6;
                    float b3 = t3 * C6;
                    const float* Cr = C2 + row * 33 + col;
                    float g = S2[col] * (x * sigmoidf_(x));
                    g = fmaf(b0, Cr[0], g);
                    g = fmaf(b1, Cr[33], g);
                    g = fmaf(b2, Cr[66], g);
                    g = fmaf(b3, Cr[99], g);
                    ps[mt * 2 + (e >> 1)] += g;
                }
#pragma unroll
        for (int s = 0; s < 4; s++) {
            ps[s] += __shfl_xor_sync(0xffffffffu, ps[s], 1);
            ps[s] += __shfl_xor_sync(0xffffffffu, ps[s], 2);
        }
        if ((lane & 3) == 0) {
#pragma unroll
            for (int s = 0; s < 4; s++) {
                int row = 16 * (s >> 1) + 8 * (s & 1) + (lane >> 2);
                out[pbase + row] = sigmoidf_(ps[s] + bias);
            }
        }
    }
}

extern "C" void kernel_launch(void* const* d_in, const int* in_sizes, int n_in,
                              void* d_out, int out_size)
{
    // order: coords, grid0, coef0, sb0, sp0, grid1, coef1, sb1, sp1, grid2, coef2, sb2, sp2, density_bias
    const float* coords = (const float*)d_in[0];
    const float* coef0  = (const float*)d_in[2];
    const float* sb0    = (const float*)d_in[3];
    const float* sp0    = (const float*)d_in[4];
    const float* coef1  = (const float*)d_in[6];
    const float* sb1    = (const float*)d_in[7];
    const float* sp1    = (const float*)d_in[8];
    const float* coef2  = (const float*)d_in[10];
    const float* sb2    = (const float*)d_in[11];
    const float* sp2    = (const float*)d_in[12];
    const float* dbias  = (const float*)d_in[13];
    float* out = (float*)d_out;

    cudaFuncSetAttribute(kan_forward, cudaFuncAttributeMaxDynamicSharedMemorySize, SMEM_BYTES);
    kan_forward<<<BLOCKS, THREADS, SMEM_BYTES>>>(coords,
                                                 coef0, sb0, sp0,
                                                 coef1, sb1, sp1,
                                                 coef2, sb2, sp2,
                                                 dbias, out);
}

// round 10
// speedup vs baseline: 1.9423x; 1.1049x over previous
#include <cuda_runtime.h>
#include <cuda_fp16.h>
#include <cstdint>

#define THREADS 128
#define BLOCKS  592               // 148 SMs * 4 CTAs
#define NPTS    (512 * 512)
#define NTILES  2048              // 128 points per block-tile

// ---- smem byte layout ----
#define OFF_BFRAG 0               // 32 kt x 4 nt x 256B (reg-interleaved) = 32768
#define OFF_ABUF  32768           // 4 warps x 32 rows x 128B = 16384
#define OFF_L0    49152           // 2 x 14 rows x 34 floats = 952 f = 3808B (row13 = sb0)
#define OFF_L2    52960           // 23 rows x 33 floats = 759 f = 3036B (zero-padded ext)
#define OFF_L2SB  55996           // 32 f = 128B
#define SMEM_BYTES 56128          // x4 CTAs = 224512

// ---------------- helpers ----------------
__device__ __forceinline__ uint32_t smem_u32(const void* p) {
    uint32_t a;
    asm("{ .reg .u64 t; cvta.to.shared.u64 t, %1; cvt.u32.u64 %0, t; }" : "=r"(a) : "l"(p));
    return a;
}
__device__ __forceinline__ void sts32(uint32_t a, uint32_t v) {
    asm volatile("st.shared.b32 [%0], %1;" :: "r"(a), "r"(v) : "memory");
}
__device__ __forceinline__ void sts16(uint32_t a, uint16_t v) {
    asm volatile("st.shared.b16 [%0], %1;" :: "r"(a), "h"(v) : "memory");
}
__device__ __forceinline__ void sts128z(uint32_t a) {
    asm volatile("st.shared.v4.b32 [%0], {%1,%1,%1,%1};" :: "r"(a), "r"(0u) : "memory");
}
__device__ __forceinline__ void lds64(uint32_t& v0, uint32_t& v1, uint32_t a) {
    asm volatile("ld.shared.v2.b32 {%0,%1}, [%2];" : "=r"(v0), "=r"(v1) : "r"(a));
}
__device__ __forceinline__ float2 lds_f2(uint32_t a) {
    float2 v;
    asm volatile("ld.shared.v2.f32 {%0,%1}, [%2];" : "=f"(v.x), "=f"(v.y) : "r"(a));
    return v;
}
__device__ __forceinline__ void ldmatrix_x4(uint32_t& r0, uint32_t& r1, uint32_t& r2, uint32_t& r3,
                                            uint32_t addr) {
    asm volatile("ldmatrix.sync.aligned.m8n8.x4.shared.b16 {%0,%1,%2,%3}, [%4];"
                 : "=r"(r0), "=r"(r1), "=r"(r2), "=r"(r3) : "r"(addr));
}
__device__ __forceinline__ void mma16816(float* d, const uint32_t* a, uint32_t b0, uint32_t b1) {
    asm volatile("mma.sync.aligned.m16n8k16.row.col.f32.f16.f16.f32 "
                 "{%0,%1,%2,%3}, {%4,%5,%6,%7}, {%8,%9}, {%0,%1,%2,%3};"
                 : "+f"(d[0]), "+f"(d[1]), "+f"(d[2]), "+f"(d[3])
                 : "r"(a[0]), "r"(a[1]), "r"(a[2]), "r"(a[3]), "r"(b0), "r"(b1));
}
// packed dual-fma: acc += s * c (s broadcast), via fma.rn.f32x2
__device__ __forceinline__ void ffma2(float2& acc, float s, float2 c) {
    asm("{\n\t"
        ".reg .b64 ra, rb, rc;\n\t"
        "mov.b64 ra, {%2,%2};\n\t"
        "mov.b64 rb, {%3,%4};\n\t"
        "mov.b64 rc, {%0,%1};\n\t"
        "fma.rn.f32x2 rc, ra, rb, rc;\n\t"
        "mov.b64 {%0,%1}, rc;\n\t"
        "}"
        : "+f"(acc.x), "+f"(acc.y)
        : "f"(s), "f"(c.x), "f"(c.y));
}
__device__ __forceinline__ float sigmoidf_(float x) { return 1.0f / (1.0f + __expf(-x)); }
__device__ __forceinline__ uint32_t h2bits(float lo, float hi) {
    __half2 h = __floats2half2_rn(lo, hi);
    return *reinterpret_cast<uint32_t*>(&h);
}

// raw uniform cubic B-spline polys (no tap zeroing); oor -> j=-3, t=0
__device__ __forceinline__ void spline_raw(float x, float& b0, float& b1, float& b2, float& b3,
                                           int& j)
{
    float u = x * 10.0f;
    bool inr = (u >= -3.0f) && (u < 13.0f);
    float uc = inr ? u : 0.0f;
    float f = floorf(uc);
    float t = uc - f;
    j = inr ? (int)f : -3;
    if (!inr) t = 0.0f;
    const float C6 = 0.16666667f;
    float t2 = t * t, t3 = t2 * t;
    float omt = 1.0f - t;
    b0 = omt * omt * omt * C6;
    b1 = (3.0f * t3 - 6.0f * t2 + 4.0f) * C6;
    b2 = ((3.0f - 3.0f * t) * t2 + 3.0f * t + 1.0f) * C6;
    b3 = t3 * C6;
}

__global__ void __launch_bounds__(THREADS, 4)
kan_forward(const float* __restrict__ coords,
            const float* __restrict__ coef0, const float* __restrict__ sb0, const float* __restrict__ sp0,
            const float* __restrict__ coef1, const float* __restrict__ sb1, const float* __restrict__ sp1,
            const float* __restrict__ coef2, const float* __restrict__ sb2, const float* __restrict__ sp2,
            const float* __restrict__ dbias,
            float* __restrict__ out)
{
    extern __shared__ char smem[];
    float* smf = reinterpret_cast<float*>(smem);
    const uint32_t sbase = smem_u32(smem);
    const int tid  = threadIdx.x;
    const int wid  = tid >> 5;
    const int lane = tid & 31;

    // ======== one-time staging ========
    // layer0 table: [i][row][o2], row 0..12 = taps (sp folded), row 13 = sb0; stride 34
    for (int idx = tid; idx < 952; idx += THREADS) {
        int i = idx / 476, r = idx % 476, k = r / 34, o = r % 34;
        float v = 0.0f;
        if (o < 32) {
            if (k < 13)      v = sp0[i * 32 + o] * coef0[(i * 32 + o) * 13 + k];
            else             v = sb0[i * 32 + o];
        }
        smf[OFF_L0 / 4 + idx] = v;
    }
    // layer2 extended table: rows 0..22, stride 33; rows 3..15 = C2[k=row-3], else 0
    for (int idx = tid; idx < 759; idx += THREADS) {
        int r = idx / 33, i = idx % 33;
        float v = 0.0f;
        int k = r - 3;
        if (i < 32 && k >= 0 && k <= 12) v = sp2[i] * coef2[i * 13 + k];
        smf[OFF_L2 / 4 + idx] = v;
    }
    for (int idx = tid; idx < 32; idx += THREADS)
        smf[OFF_L2SB / 4 + idx] = sb2[idx];
    // layer1 B in mma fragment layout, fp16, reg-interleaved (lane*8 + reg*4)
    for (int e = tid; e < 8192; e += THREADS) {
        int L = e & 31, reg = (e >> 5) & 1, nt = (e >> 6) & 3, kt = e >> 8;
        int k = kt * 16 + 2 * (L & 3) + 8 * reg;
        int n = nt * 8 + (L >> 2);
        float w[2];
#pragma unroll
        for (int z = 0; z < 2; z++) {
            int f = k + z;
            int i = f >> 4, r = f & 15;
            float v = 0.0f;
            if (r == 0)       v = sb1[i * 32 + n];
            else if (r <= 13) v = sp1[i * 32 + n] * coef1[(i * 32 + n) * 13 + (r - 1)];
            w[z] = v;
        }
        uint32_t addr = sbase + OFF_BFRAG + (uint32_t)((kt * 4 + nt) * 256 + L * 8 + reg * 4);
        sts32(addr, h2bits(w[0], w[1]));
    }
    __syncthreads();

    const float bias = dbias[0];
    const uint32_t ABw     = sbase + OFF_ABUF + (uint32_t)wid * 4096u;
    const uint32_t rowbase = ABw + (uint32_t)lane * 128u;
    const uint32_t swzm    = (uint32_t)(lane & 7) << 4;
    const int lrow  = lane & 15;
    const int lcolb = (lane >> 4) * 16;
    const uint32_t rmask = (uint32_t)(lrow & 7) << 4;
    const uint32_t lmA0 = ABw + (uint32_t)lrow * 128u;
    const uint32_t lmA1 = ABw + (uint32_t)(16 + lrow) * 128u;

    for (int tile = blockIdx.x; tile < NTILES; tile += gridDim.x) {
        const int pbase = tile * 128 + wid * 32;
        const int p = pbase + lane;

        // ---- layer-0 prep: bases + taps + table row addresses (coords in [0,1)) ----
        float2 cc = reinterpret_cast<const float2*>(coords)[p];
        float tb[2][4], bas[2];
        uint32_t Trow[2][5];
#pragma unroll
        for (int i = 0; i < 2; i++) {
            float x = (i == 0) ? cc.x : cc.y;
            float u = x * 10.0f;
            float fl = floorf(u);
            float t = u - fl;
            int j = (int)fl;                 // 0..9
            const float C6 = 0.16666667f;
            float t2 = t * t, t3 = t2 * t;
            float omt = 1.0f - t;
            tb[i][0] = omt * omt * omt * C6;
            tb[i][1] = (3.0f * t3 - 6.0f * t2 + 4.0f) * C6;
            tb[i][2] = ((3.0f - 3.0f * t) * t2 + 3.0f * t + 1.0f) * C6;
            tb[i][3] = t3 * C6;
            bas[i] = x * sigmoidf_(x);
            uint32_t Ai = sbase + OFF_L0 + (uint32_t)i * 1904u;
            uint32_t r0 = Ai + (uint32_t)j * 136u;
            Trow[i][0] = r0;
            Trow[i][1] = r0 + 136u;
            Trow[i][2] = r0 + 272u;
            Trow[i][3] = r0 + 408u;
            Trow[i][4] = Ai + 1768u;         // sb0 row
        }

        // zero + compute h1 for 4 outputs + scatter, for chunk cidx (into my A row)
        auto do_chunk = [&](int cidx) {
#pragma unroll
            for (int q = 0; q < 8; q++)
                sts128z(rowbase + (((uint32_t)q * 16u) ^ swzm));
            float xv[4];
#pragma unroll
            for (int z = 0; z < 2; z++) {
                uint32_t off = (uint32_t)(2 * cidx + z) * 8u;
                float2 h = make_float2(0.0f, 0.0f);
#pragma unroll
                for (int i = 0; i < 2; i++) {
                    ffma2(h, bas[i],   lds_f2(Trow[i][4] + off));
                    ffma2(h, tb[i][0], lds_f2(Trow[i][0] + off));
                    ffma2(h, tb[i][1], lds_f2(Trow[i][1] + off));
                    ffma2(h, tb[i][2], lds_f2(Trow[i][2] + off));
                    ffma2(h, tb[i][3], lds_f2(Trow[i][3] + off));
                }
                xv[2 * z] = h.x;
                xv[2 * z + 1] = h.y;
            }
            // guard-free scatter (invalid taps absorbed by wi guards / dummy slots /
            // slot 0 overwritten by silu)
#pragma unroll
            for (int il = 0; il < 4; il++) {
                float x = xv[il];
                float b0, b1, b2, b3; int j;
                spline_raw(x, b0, b1, b2, b3, j);
                float base = x * sigmoidf_(x);
                uint32_t u01 = h2bits(b0, b1);
                uint32_t u23 = h2bits(b2, b3);
                int s1 = 1 + j;               // slot of first tap, in [-2, 13]
                int wi = s1 >> 1;             // word of first tap, in [-1, 6]
                bool odd = (s1 & 1) != 0;
                uint32_t v1 = odd ? (u01 << 16) : u01;
                uint32_t v2 = odd ? ((u01 >> 16) | (u23 << 16)) : u23;
                uint32_t v3 = odd ? (u23 >> 16) : 0u;
                uint32_t bb = (uint32_t)(32 * il);
                if (wi >= 0) sts32(rowbase + ((bb + 4u * (uint32_t)wi) ^ swzm), v1);
                sts32(rowbase + ((bb + 4u * (uint32_t)(wi + 1)) ^ swzm), v2);
                if (wi <= 5) sts32(rowbase + ((bb + 4u * (uint32_t)(wi + 2)) ^ swzm), v3);
                __half hs = __float2half_rn(base);
                sts16(rowbase + (bb ^ swzm), __half_as_ushort(hs));
            }
        };

        // ---- layer 1: pipelined GEMM D[32x32] = A[32x512] * B ----
        float acc[2][4][4];
#pragma unroll
        for (int mt = 0; mt < 2; mt++)
#pragma unroll
            for (int nt = 0; nt < 4; nt++)
#pragma unroll
                for (int e = 0; e < 4; e++) acc[mt][nt][e] = 0.0f;

        do_chunk(0);

#pragma unroll 1
        for (int c = 0; c < 8; c++) {
            __syncwarp();                 // scatter(c) visible to all lanes
            uint32_t afr[4][2][4];
#pragma unroll
            for (int kt = 0; kt < 4; kt++) {
                uint32_t inrow = ((uint32_t)(kt * 32 + lcolb)) ^ rmask;
                ldmatrix_x4(afr[kt][0][0], afr[kt][0][1], afr[kt][0][2], afr[kt][0][3],
                            lmA0 + inrow);
                ldmatrix_x4(afr[kt][1][0], afr[kt][1][1], afr[kt][1][2], afr[kt][1][3],
                            lmA1 + inrow);
            }
            __syncwarp();                 // all A reads done -> buffer reusable
            if (c < 7) do_chunk(c + 1);   // overlaps with mma below
#pragma unroll
            for (int kt = 0; kt < 4; kt++) {
                int ktg = c * 4 + kt;
#pragma unroll
                for (int nt = 0; nt < 4; nt++) {
                    uint32_t b0, b1;
                    lds64(b0, b1, sbase + OFF_BFRAG
                                  + (uint32_t)((ktg * 4 + nt) * 256 + lane * 8));
                    mma16816(acc[0][nt], afr[kt][0], b0, b1);
                    mma16816(acc[1][nt], afr[kt][1], b0, b1);
                }
            }
        }

        // ---- layer 2 in fragment space (extended zero-padded table, no clamps) ----
        const float* C2 = smf + OFF_L2 / 4;
        const float* S2 = smf + OFF_L2SB / 4;
        float ps[4] = {0.0f, 0.0f, 0.0f, 0.0f};
#pragma unroll
        for (int mt = 0; mt < 2; mt++)
#pragma unroll
            for (int nt = 0; nt < 4; nt++)
#pragma unroll
                for (int e = 0; e < 4; e++) {
                    float x = acc[mt][nt][e];
                    int col = nt * 8 + 2 * (lane & 3) + (e & 1);
                    float u = x * 10.0f;
                    bool inr = (u >= -3.0f) && (u < 13.0f);
                    float uc = inr ? u : 0.0f;
                    float fl = floorf(uc);
                    float t = uc - fl;
                    int row = inr ? ((int)fl + 3) : 19;
                    const float C6 = 0.16666667f;
                    float t2 = t * t, t3 = t2 * t;
                    float omt = 1.0f - t;
                    float b0 = omt * omt * omt * C6;
                    float b1 = (3.0f * t3 - 6.0f * t2 + 4.0f) * C6;
                    float b2 = ((3.0f - 3.0f * t) * t2 + 3.0f * t + 1.0f) * C6;
                    float b3 = t3 * C6;
                    const float* Cr = C2 + row * 33 + col;
                    float g = S2[col] * (x * sigmoidf_(x));
                    g = fmaf(b0, Cr[0], g);
                    g = fmaf(b1, Cr[33], g);
                    g = fmaf(b2, Cr[66], g);
                    g = fmaf(b3, Cr[99], g);
                    ps[mt * 2 + (e >> 1)] += g;
                }
#pragma unroll
        for (int s = 0; s < 4; s++) {
            ps[s] += __shfl_xor_sync(0xffffffffu, ps[s], 1);
            ps[s] += __shfl_xor_sync(0xffffffffu, ps[s], 2);
        }
        if ((lane & 3) == 0) {
#pragma unroll
            for (int s = 0; s < 4; s++) {
                int row = 16 * (s >> 1) + 8 * (s & 1) + (lane >> 2);
                out[pbase + row] = sigmoidf_(ps[s] + bias);
            }
        }
    }
}

extern "C" void kernel_launch(void* const* d_in, const int* in_sizes, int n_in,
                              void* d_out, int out_size)
{
    // order: coords, grid0, coef0, sb0, sp0, grid1, coef1, sb1, sp1, grid2, coef2, sb2, sp2, density_bias
    const float* coords = (const float*)d_in[0];
    const float* coef0  = (const float*)d_in[2];
    const float* sb0    = (const float*)d_in[3];
    const float* sp0    = (const float*)d_in[4];
    const float* coef1  = (const float*)d_in[6];
    const float* sb1    = (const float*)d_in[7];
    const float* sp1    = (const float*)d_in[8];
    const float* coef2  = (const float*)d_in[10];
    const float* sb2    = (const float*)d_in[11];
    const float* sp2    = (const float*)d_in[12];
    const float* dbias  = (const float*)d_in[13];
    float* out = (float*)d_out;

    cudaFuncSetAttribute(kan_forward, cudaFuncAttributeMaxDynamicSharedMemorySize, SMEM_BYTES);
    kan_forward<<<BLOCKS, THREADS, SMEM_BYTES>>>(coords,
                                                 coef0, sb0, sp0,
                                                 coef1, sb1, sp1,
                                                 coef2, sb2, sp2,
                                                 dbias, out);
}

// round 11
// speedup vs baseline: 1.9895x; 1.0243x over previous
#include <cuda_runtime.h>
#include <cuda_fp16.h>
#include <cstdint>

#define THREADS 128
#define BLOCKS  592               // 148 SMs * 4 CTAs
#define NPTS    (512 * 512)
#define NTILES  2048              // 128 points per block-tile

// ---- smem byte layout ----
#define OFF_BFRAG 0               // 32 kt x 2 npair x 512B (16B-grouped) = 32768
#define OFF_ABUF  32768           // 4 warps x 32 rows x 128B = 16384
#define OFF_L0    49152           // 2 x 14 rows x 34 floats = 952 f = 3808B (row13 = sb0)
#define OFF_L2    52960           // 23 rows x 33 floats = 759 f = 3036B (zero-padded ext)
#define OFF_L2SB  55996           // 32 f = 128B
#define SMEM_BYTES 56128          // x4 CTAs = 224512

// ---------------- helpers ----------------
__device__ __forceinline__ uint32_t smem_u32(const void* p) {
    uint32_t a;
    asm("{ .reg .u64 t; cvta.to.shared.u64 t, %1; cvt.u32.u64 %0, t; }" : "=r"(a) : "l"(p));
    return a;
}
__device__ __forceinline__ void sts32(uint32_t a, uint32_t v) {
    asm volatile("st.shared.b32 [%0], %1;" :: "r"(a), "r"(v) : "memory");
}
__device__ __forceinline__ void sts16(uint32_t a, uint16_t v) {
    asm volatile("st.shared.b16 [%0], %1;" :: "r"(a), "h"(v) : "memory");
}
__device__ __forceinline__ void sts128z(uint32_t a) {
    asm volatile("st.shared.v4.b32 [%0], {%1,%1,%1,%1};" :: "r"(a), "r"(0u) : "memory");
}
__device__ __forceinline__ void lds128(uint32_t& v0, uint32_t& v1, uint32_t& v2, uint32_t& v3,
                                       uint32_t a) {
    asm volatile("ld.shared.v4.b32 {%0,%1,%2,%3}, [%4];"
                 : "=r"(v0), "=r"(v1), "=r"(v2), "=r"(v3) : "r"(a));
}
__device__ __forceinline__ void ldmatrix_x4(uint32_t& r0, uint32_t& r1, uint32_t& r2, uint32_t& r3,
                                            uint32_t addr) {
    asm volatile("ldmatrix.sync.aligned.m8n8.x4.shared.b16 {%0,%1,%2,%3}, [%4];"
                 : "=r"(r0), "=r"(r1), "=r"(r2), "=r"(r3) : "r"(addr));
}
__device__ __forceinline__ void mma16816(float* d, const uint32_t* a, uint32_t b0, uint32_t b1) {
    asm volatile("mma.sync.aligned.m16n8k16.row.col.f32.f16.f16.f32 "
                 "{%0,%1,%2,%3}, {%4,%5,%6,%7}, {%8,%9}, {%0,%1,%2,%3};"
                 : "+f"(d[0]), "+f"(d[1]), "+f"(d[2]), "+f"(d[3])
                 : "r"(a[0]), "r"(a[1]), "r"(a[2]), "r"(a[3]), "r"(b0), "r"(b1));
}
// packed f32x2 on native 64-bit register pairs (no per-op movs)
typedef unsigned long long u64;
__device__ __forceinline__ u64 pack2(float lo, float hi) {
    u64 r;
    asm("mov.b64 %0, {%1,%2};" : "=l"(r) : "f"(lo), "f"(hi));
    return r;
}
__device__ __forceinline__ u64 lds_b64(uint32_t a) {
    u64 v;
    asm volatile("ld.shared.b64 %0, [%1];" : "=l"(v) : "r"(a));
    return v;
}
__device__ __forceinline__ void fma2(u64& acc, u64 a, u64 b) {
    asm("fma.rn.f32x2 %0, %1, %2, %0;" : "+l"(acc) : "l"(a), "l"(b));
}
__device__ __forceinline__ void unpack2(u64 v, float& lo, float& hi) {
    asm("mov.b64 {%0,%1}, %2;" : "=f"(lo), "=f"(hi) : "l"(v));
}
__device__ __forceinline__ float sigmoidf_(float x) { return 1.0f / (1.0f + __expf(-x)); }
__device__ __forceinline__ uint32_t h2bits(float lo, float hi) {
    __half2 h = __floats2half2_rn(lo, hi);
    return *reinterpret_cast<uint32_t*>(&h);
}

// raw uniform cubic B-spline polys (no tap zeroing); oor -> j=-3, t=0
__device__ __forceinline__ void spline_raw(float x, float& b0, float& b1, float& b2, float& b3,
                                           int& j)
{
    float u = x * 10.0f;
    bool inr = (u >= -3.0f) && (u < 13.0f);
    float uc = inr ? u : 0.0f;
    float f = floorf(uc);
    float t = uc - f;
    j = inr ? (int)f : -3;
    if (!inr) t = 0.0f;
    const float C6 = 0.16666667f;
    float t2 = t * t, t3 = t2 * t;
    float omt = 1.0f - t;
    b0 = omt * omt * omt * C6;
    b1 = (3.0f * t3 - 6.0f * t2 + 4.0f) * C6;
    b2 = ((3.0f - 3.0f * t) * t2 + 3.0f * t + 1.0f) * C6;
    b3 = t3 * C6;
}

__global__ void __launch_bounds__(THREADS, 4)
kan_forward(const float* __restrict__ coords,
            const float* __restrict__ coef0, const float* __restrict__ sb0, const float* __restrict__ sp0,
            const float* __restrict__ coef1, const float* __restrict__ sb1, const float* __restrict__ sp1,
            const float* __restrict__ coef2, const float* __restrict__ sb2, const float* __restrict__ sp2,
            const float* __restrict__ dbias,
            float* __restrict__ out)
{
    extern __shared__ char smem[];
    float* smf = reinterpret_cast<float*>(smem);
    const uint32_t sbase = smem_u32(smem);
    const int tid  = threadIdx.x;
    const int wid  = tid >> 5;
    const int lane = tid & 31;

    // ======== one-time staging ========
    // layer0 table: [i][row][o2], row 0..12 = taps (sp folded), row 13 = sb0; stride 34
    for (int idx = tid; idx < 952; idx += THREADS) {
        int i = idx / 476, r = idx % 476, k = r / 34, o = r % 34;
        float v = 0.0f;
        if (o < 32) {
            if (k < 13)      v = sp0[i * 32 + o] * coef0[(i * 32 + o) * 13 + k];
            else             v = sb0[i * 32 + o];
        }
        smf[OFF_L0 / 4 + idx] = v;
    }
    // layer2 extended table: rows 0..22, stride 33; rows 3..15 = C2[k=row-3], else 0
    for (int idx = tid; idx < 759; idx += THREADS) {
        int r = idx / 33, i = idx % 33;
        float v = 0.0f;
        int k = r - 3;
        if (i < 32 && k >= 0 && k <= 12) v = sp2[i] * coef2[i * 13 + k];
        smf[OFF_L2 / 4 + idx] = v;
    }
    for (int idx = tid; idx < 32; idx += THREADS)
        smf[OFF_L2SB / 4 + idx] = sb2[idx];
    // layer1 B in mma fragment layout, fp16, 16B-grouped:
    // addr = (kt*2+npair)*512 + L*16 + ((nt&1)*2+reg)*4
    for (int e = tid; e < 8192; e += THREADS) {
        int L = e & 31, reg = (e >> 5) & 1, nt = (e >> 6) & 3, kt = e >> 8;
        int k = kt * 16 + 2 * (L & 3) + 8 * reg;
        int n = nt * 8 + (L >> 2);
        float w[2];
#pragma unroll
        for (int z = 0; z < 2; z++) {
            int f = k + z;
            int i = f >> 4, r = f & 15;
            float v = 0.0f;
            if (r == 0)       v = sb1[i * 32 + n];
            else if (r <= 13) v = sp1[i * 32 + n] * coef1[(i * 32 + n) * 13 + (r - 1)];
            w[z] = v;
        }
        uint32_t addr = sbase + OFF_BFRAG
                      + (uint32_t)((kt * 2 + (nt >> 1)) * 512 + L * 16 + ((nt & 1) * 2 + reg) * 4);
        sts32(addr, h2bits(w[0], w[1]));
    }
    __syncthreads();

    const float bias = dbias[0];
    const uint32_t ABw     = sbase + OFF_ABUF + (uint32_t)wid * 4096u;
    const uint32_t rowbase = ABw + (uint32_t)lane * 128u;
    const uint32_t swzm    = (uint32_t)(lane & 7) << 4;
    const int lrow  = lane & 15;
    const int lcolb = (lane >> 4) * 16;
    const uint32_t rmask = (uint32_t)(lrow & 7) << 4;
    const uint32_t lmA0 = ABw + (uint32_t)lrow * 128u;
    const uint32_t lmA1 = ABw + (uint32_t)(16 + lrow) * 128u;
    const uint32_t bfr_lane = sbase + OFF_BFRAG + (uint32_t)lane * 16u;

    for (int tile = blockIdx.x; tile < NTILES; tile += gridDim.x) {
        const int pbase = tile * 128 + wid * 32;
        const int p = pbase + lane;

        // ---- layer-0 prep: packed broadcast scalars + table row base addrs ----
        float2 cc = reinterpret_cast<const float2*>(coords)[p];
        u64 Sp[2][5];
        uint32_t Tr[2];                  // base addr of tap row j; TS row at Ai+1768 (imm)
#pragma unroll
        for (int i = 0; i < 2; i++) {
            float x = (i == 0) ? cc.x : cc.y;
            float u = x * 10.0f;
            float fl = floorf(u);
            float t = u - fl;
            int j = (int)fl;                 // 0..9 (coords in [0,1))
            const float C6 = 0.16666667f;
            float t2 = t * t, t3 = t2 * t;
            float omt = 1.0f - t;
            float b0 = omt * omt * omt * C6;
            float b1 = (3.0f * t3 - 6.0f * t2 + 4.0f) * C6;
            float b2 = ((3.0f - 3.0f * t) * t2 + 3.0f * t + 1.0f) * C6;
            float b3 = t3 * C6;
            float base = x * sigmoidf_(x);
            Sp[i][0] = pack2(base, base);
            Sp[i][1] = pack2(b0, b0);
            Sp[i][2] = pack2(b1, b1);
            Sp[i][3] = pack2(b2, b2);
            Sp[i][4] = pack2(b3, b3);
            Tr[i] = sbase + OFF_L0 + (uint32_t)i * 1904u + (uint32_t)j * 136u;
        }
        const uint32_t TS0 = sbase + OFF_L0 + 1768u;
        const uint32_t TS1 = sbase + OFF_L0 + 1904u + 1768u;

        // zero + compute h1 for 4 outputs + scatter, for chunk cidx (into my A row)
        auto do_chunk = [&](int cidx) {
#pragma unroll
            for (int q = 0; q < 8; q++)
                sts128z(rowbase + (((uint32_t)q * 16u) ^ swzm));
            float xv[4];
#pragma unroll
            for (int z = 0; z < 2; z++) {
                uint32_t off = (uint32_t)(2 * cidx + z) * 8u;
                u64 h = 0ull;
                fma2(h, Sp[0][0], lds_b64(TS0 + off));
                fma2(h, Sp[0][1], lds_b64(Tr[0] + off));
                fma2(h, Sp[0][2], lds_b64(Tr[0] + 136u + off));
                fma2(h, Sp[0][3], lds_b64(Tr[0] + 272u + off));
                fma2(h, Sp[0][4], lds_b64(Tr[0] + 408u + off));
                fma2(h, Sp[1][0], lds_b64(TS1 + off));
                fma2(h, Sp[1][1], lds_b64(Tr[1] + off));
                fma2(h, Sp[1][2], lds_b64(Tr[1] + 136u + off));
                fma2(h, Sp[1][3], lds_b64(Tr[1] + 272u + off));
                fma2(h, Sp[1][4], lds_b64(Tr[1] + 408u + off));
                unpack2(h, xv[2 * z], xv[2 * z + 1]);
            }
            // guard-free scatter (invalid taps absorbed by wi guards / dummy slots /
            // slot 0 overwritten by silu)
#pragma unroll
            for (int il = 0; il < 4; il++) {
                float x = xv[il];
                float b0, b1, b2, b3; int j;
                spline_raw(x, b0, b1, b2, b3, j);
                float base = x * sigmoidf_(x);
                uint32_t u01 = h2bits(b0, b1);
                uint32_t u23 = h2bits(b2, b3);
                int s1 = 1 + j;               // slot of first tap, in [-2, 13]
                int wi = s1 >> 1;             // word of first tap, in [-1, 6]
                bool odd = (s1 & 1) != 0;
                uint32_t v1 = odd ? (u01 << 16) : u01;
                uint32_t v2 = odd ? ((u01 >> 16) | (u23 << 16)) : u23;
                uint32_t v3 = odd ? (u23 >> 16) : 0u;
                uint32_t bb = (uint32_t)(32 * il);
                if (wi >= 0) sts32(rowbase + ((bb + 4u * (uint32_t)wi) ^ swzm), v1);
                sts32(rowbase + ((bb + 4u * (uint32_t)(wi + 1)) ^ swzm), v2);
                if (wi <= 5) sts32(rowbase + ((bb + 4u * (uint32_t)(wi + 2)) ^ swzm), v3);
                __half hs = __float2half_rn(base);
                sts16(rowbase + (bb ^ swzm), __half_as_ushort(hs));
            }
        };

        // ---- layer 1: pipelined GEMM D[32x32] = A[32x512] * B ----
        float acc[2][4][4];
#pragma unroll
        for (int mt = 0; mt < 2; mt++)
#pragma unroll
            for (int nt = 0; nt < 4; nt++)
#pragma unroll
                for (int e = 0; e < 4; e++) acc[mt][nt][e] = 0.0f;

        do_chunk(0);

#pragma unroll 1
        for (int c = 0; c < 8; c++) {
            __syncwarp();                 // scatter(c) visible to all lanes
            uint32_t afr[4][2][4];
#pragma unroll
            for (int kt = 0; kt < 4; kt++) {
                uint32_t inrow = ((uint32_t)(kt * 32 + lcolb)) ^ rmask;
                ldmatrix_x4(afr[kt][0][0], afr[kt][0][1], afr[kt][0][2], afr[kt][0][3],
                            lmA0 + inrow);
                ldmatrix_x4(afr[kt][1][0], afr[kt][1][1], afr[kt][1][2], afr[kt][1][3],
                            lmA1 + inrow);
            }
            __syncwarp();                 // all A reads done -> buffer reusable
            if (c < 7) do_chunk(c + 1);   // overlaps with mma below
#pragma unroll
            for (int kt = 0; kt < 4; kt++) {
                int ktg = c * 4 + kt;
#pragma unroll
                for (int np = 0; np < 2; np++) {
                    uint32_t b00, b01, b10, b11;
                    lds128(b00, b01, b10, b11,
                           bfr_lane + (uint32_t)((ktg * 2 + np) * 512));
                    mma16816(acc[0][2 * np],     afr[kt][0], b00, b01);
                    mma16816(acc[1][2 * np],     afr[kt][1], b00, b01);
                    mma16816(acc[0][2 * np + 1], afr[kt][0], b10, b11);
                    mma16816(acc[1][2 * np + 1], afr[kt][1], b10, b11);
                }
            }
        }

        // ---- layer 2 in fragment space (extended zero-padded table, no clamps) ----
        const float* C2 = smf + OFF_L2 / 4;
        const float* S2 = smf + OFF_L2SB / 4;
        float ps[4] = {0.0f, 0.0f, 0.0f, 0.0f};
#pragma unroll
        for (int mt = 0; mt < 2; mt++)
#pragma unroll
            for (int nt = 0; nt < 4; nt++)
#pragma unroll
                for (int e = 0; e < 4; e++) {
                    float x = acc[mt][nt][e];
                    int col = nt * 8 + 2 * (lane & 3) + (e & 1);
                    float u = x * 10.0f;
                    bool inr = (u >= -3.0f) && (u < 13.0f);
                    float uc = inr ? u : 0.0f;
                    float fl = floorf(uc);
                    float t = uc - fl;
                    int row = inr ? ((int)fl + 3) : 19;
                    const float C6 = 0.16666667f;
                    float t2 = t * t, t3 = t2 * t;
                    float omt = 1.0f - t;
                    float b0 = omt * omt * omt * C6;
                    float b1 = (3.0f * t3 - 6.0f * t2 + 4.0f) * C6;
                    float b2 = ((3.0f - 3.0f * t) * t2 + 3.0f * t + 1.0f) * C6;
                    float b3 = t3 * C6;
                    const float* Cr = C2 + row * 33 + col;
                    float g = S2[col] * (x * sigmoidf_(x));
                    g = fmaf(b0, Cr[0], g);
                    g = fmaf(b1, Cr[33], g);
                    g = fmaf(b2, Cr[66], g);
                    g = fmaf(b3, Cr[99], g);
                    ps[mt * 2 + (e >> 1)] += g;
                }
#pragma unroll
        for (int s = 0; s < 4; s++) {
            ps[s] += __shfl_xor_sync(0xffffffffu, ps[s], 1);
            ps[s] += __shfl_xor_sync(0xffffffffu, ps[s], 2);
        }
        if ((lane & 3) == 0) {
#pragma unroll
            for (int s = 0; s < 4; s++) {
                int row = 16 * (s >> 1) + 8 * (s & 1) + (lane >> 2);
                out[pbase + row] = sigmoidf_(ps[s] + bias);
            }
        }
    }
}

extern "C" void kernel_launch(void* const* d_in, const int* in_sizes, int n_in,
                              void* d_out, int out_size)
{
    // order: coords, grid0, coef0, sb0, sp0, grid1, coef1, sb1, sp1, grid2, coef2, sb2, sp2, density_bias
    const float* coords = (const float*)d_in[0];
    const float* coef0  = (const float*)d_in[2];
    const float* sb0    = (const float*)d_in[3];
    const float* sp0    = (const float*)d_in[4];
    const float* coef1  = (const float*)d_in[6];
    const float* sb1    = (const float*)d_in[7];
    const float* sp1    = (const float*)d_in[8];
    const float* coef2  = (const float*)d_in[10];
    const float* sb2    = (const float*)d_in[11];
    const float* sp2    = (const float*)d_in[12];
    const float* dbias  = (const float*)d_in[13];
    float* out = (float*)d_out;

    cudaFuncSetAttribute(kan_forward, cudaFuncAttributeMaxDynamicSharedMemorySize, SMEM_BYTES);
    kan_forward<<<BLOCKS, THREADS, SMEM_BYTES>>>(coords,
                                                 coef0, sb0, sp0,
                                                 coef1, sb1, sp1,
                                                 coef2, sb2, sp2,
                                                 dbias, out);
}

// round 13
// speedup vs baseline: 2.4195x; 1.2161x over previous
#include <cuda_runtime.h>
#include <cuda_fp16.h>
#include <cstdint>

#define THREADS 128
#define BLOCKS  740               // 148 SMs * 5 CTAs
#define NPTS    (512 * 512)
#define NTILES  2048              // 128 points per block-tile

// ---- smem byte layout ----
#define OFF_ABUF  0               // 4 warps x 32 rows x 128B = 16384
#define OFF_L0    16384           // power-basis L0: 2 i x 10 j x 528B = 10560
#define OFF_L0SB  26944           // sb0 pairs: 2 i x 16 q x 8B = 256
#define OFF_L2    27200           // power-basis L2: 16 rows x 528B = 8448
#define OFF_L2SB  35648           // 32 f32 = 128
#define SMEM_BYTES 35776          // x5 CTAs fits

// B fragments live in global, cached in L1 (shared by all CTAs on an SM)
__device__ uint32_t g_bfrag[8192];

// ---------------- helpers ----------------
typedef unsigned long long u64;
__device__ __forceinline__ uint32_t smem_u32(const void* p) {
    uint32_t a;
    asm("{ .reg .u64 t; cvta.to.shared.u64 t, %1; cvt.u32.u64 %0, t; }" : "=r"(a) : "l"(p));
    return a;
}
__device__ __forceinline__ void sts32(uint32_t a, uint32_t v) {
    asm volatile("st.shared.b32 [%0], %1;" :: "r"(a), "r"(v) : "memory");
}
__device__ __forceinline__ void sts16(uint32_t a, uint16_t v) {
    asm volatile("st.shared.b16 [%0], %1;" :: "r"(a), "h"(v) : "memory");
}
__device__ __forceinline__ void sts128z(uint32_t a) {
    asm volatile("st.shared.v4.b32 [%0], {%1,%1,%1,%1};" :: "r"(a), "r"(0u) : "memory");
}
__device__ __forceinline__ void lds128f(float& a, float& b, float& c, float& d, uint32_t addr) {
    asm volatile("ld.shared.v4.f32 {%0,%1,%2,%3}, [%4];"
                 : "=f"(a), "=f"(b), "=f"(c), "=f"(d) : "r"(addr));
}
__device__ __forceinline__ void lds128u64(u64& a, u64& b, uint32_t addr) {
    asm volatile("ld.shared.v2.b64 {%0,%1}, [%2];" : "=l"(a), "=l"(b) : "r"(addr));
}
__device__ __forceinline__ u64 lds_b64(uint32_t a) {
    u64 v;
    asm volatile("ld.shared.b64 %0, [%1];" : "=l"(v) : "r"(a));
    return v;
}
__device__ __forceinline__ void ldmatrix_x4(uint32_t& r0, uint32_t& r1, uint32_t& r2, uint32_t& r3,
                                            uint32_t addr) {
    asm volatile("ldmatrix.sync.aligned.m8n8.x4.shared.b16 {%0,%1,%2,%3}, [%4];"
                 : "=r"(r0), "=r"(r1), "=r"(r2), "=r"(r3) : "r"(addr));
}
__device__ __forceinline__ void mma16816(float* d, const uint32_t* a, uint32_t b0, uint32_t b1) {
    asm volatile("mma.sync.aligned.m16n8k16.row.col.f32.f16.f16.f32 "
                 "{%0,%1,%2,%3}, {%4,%5,%6,%7}, {%8,%9}, {%0,%1,%2,%3};"
                 : "+f"(d[0]), "+f"(d[1]), "+f"(d[2]), "+f"(d[3])
                 : "r"(a[0]), "r"(a[1]), "r"(a[2]), "r"(a[3]), "r"(b0), "r"(b1));
}
__device__ __forceinline__ u64 pack2(float lo, float hi) {
    u64 r;
    asm("mov.b64 %0, {%1,%2};" : "=l"(r) : "f"(lo), "f"(hi));
    return r;
}
__device__ __forceinline__ void fma2(u64& acc, u64 a, u64 b) {
    asm("fma.rn.f32x2 %0, %1, %2, %0;" : "+l"(acc) : "l"(a), "l"(b));
}
__device__ __forceinline__ u64 fma2g(u64 a, u64 b, u64 c) {
    u64 d;
    asm("fma.rn.f32x2 %0, %1, %2, %3;" : "=l"(d) : "l"(a), "l"(b), "l"(c));
    return d;
}
__device__ __forceinline__ u64 add2(u64 a, u64 b) {
    u64 d;
    asm("add.rn.f32x2 %0, %1, %2;" : "=l"(d) : "l"(a), "l"(b));
    return d;
}
__device__ __forceinline__ void unpack2(u64 v, float& lo, float& hi) {
    asm("mov.b64 {%0,%1}, %2;" : "=f"(lo), "=f"(hi) : "l"(v));
}
__device__ __forceinline__ float sigmoidf_(float x) { return 1.0f / (1.0f + __expf(-x)); }
__device__ __forceinline__ uint32_t h2bits(float lo, float hi) {
    __half2 h = __floats2half2_rn(lo, hi);
    return *reinterpret_cast<uint32_t*>(&h);
}

// raw uniform cubic B-spline polys (no tap zeroing); oor -> j=-3, t=0
__device__ __forceinline__ void spline_raw(float x, float& b0, float& b1, float& b2, float& b3,
                                           int& j)
{
    float u = x * 10.0f;
    bool inr = (u >= -3.0f) && (u < 13.0f);
    float uc = inr ? u : 0.0f;
    float f = floorf(uc);
    float t = uc - f;
    j = inr ? (int)f : -3;
    if (!inr) t = 0.0f;
    const float C6 = 0.16666667f;
    float t2 = t * t, t3 = t2 * t;
    float omt = 1.0f - t;
    b0 = omt * omt * omt * C6;
    b1 = (3.0f * t3 - 6.0f * t2 + 4.0f) * C6;
    b2 = ((3.0f - 3.0f * t) * t2 + 3.0f * t + 1.0f) * C6;
    b3 = t3 * C6;
}

// power-basis coefficients from 4 taps C0..C3 (spline = c0 + c1 t + c2 t^2 + c3 t^3)
__device__ __forceinline__ void pb_coeffs(const float* C, float& c0, float& c1, float& c2, float& c3)
{
    const float C6 = 0.16666667f;
    c0 = (C[0] + 4.0f * C[1] + C[2]) * C6;
    c1 = (C[2] - C[0]) * 0.5f;
    c2 = (C[0] - 2.0f * C[1] + C[2]) * 0.5f;
    c3 = (-C[0] + 3.0f * C[1] - 3.0f * C[2] + C[3]) * C6;
}

// ---------------- init kernel: stage B fragments to global ----------------
__global__ void bfrag_init(const float* __restrict__ sb1, const float* __restrict__ sp1,
                           const float* __restrict__ coef1)
{
    int e = blockIdx.x * blockDim.x + threadIdx.x;
    if (e >= 8192) return;
    int L = e & 31, reg = (e >> 5) & 1, nt = (e >> 6) & 3, kt = e >> 8;
    int k = kt * 16 + 2 * (L & 3) + 8 * reg;
    int n = nt * 8 + (L >> 2);
    float w[2];
#pragma unroll
    for (int z = 0; z < 2; z++) {
        int f = k + z;
        int i = f >> 4, r = f & 15;
        float v = 0.0f;
        if (r == 0)       v = sb1[i * 32 + n];
        else if (r <= 13) v = sp1[i * 32 + n] * coef1[(i * 32 + n) * 13 + (r - 1)];
        w[z] = v;
    }
    g_bfrag[(kt * 2 + (nt >> 1)) * 128 + L * 4 + (nt & 1) * 2 + reg] = h2bits(w[0], w[1]);
}

// ---------------- main kernel ----------------
__global__ void __launch_bounds__(THREADS, 5)
kan_forward(const float* __restrict__ coords,
            const float* __restrict__ coef0, const float* __restrict__ sb0, const float* __restrict__ sp0,
            const float* __restrict__ coef2, const float* __restrict__ sb2, const float* __restrict__ sp2,
            const float* __restrict__ dbias,
            float* __restrict__ out)
{
    extern __shared__ char smem[];
    float* smf = reinterpret_cast<float*>(smem);
    const uint32_t sbase = smem_u32(smem);
    const int tid  = threadIdx.x;
    const int wid  = tid >> 5;
    const int lane = tid & 31;

    // ======== one-time staging ========
    // L0 power-basis: [i][j][q]{c3,c3',c2,c2',c1,c1',c0,c0'}; j stride 528B
    for (int idx = tid; idx < 320; idx += THREADS) {
        int i = idx / 160, r = idx % 160, j = r / 16, q = r % 16;
        int fo = (OFF_L0 + i * 5280 + j * 528 + q * 32) / 4;
#pragma unroll
        for (int z = 0; z < 2; z++) {
            int o = 2 * q + z;
            float C[4];
#pragma unroll
            for (int d = 0; d < 4; d++)
                C[d] = sp0[i * 32 + o] * coef0[(i * 32 + o) * 13 + j + d];
            float c0, c1, c2, c3;
            pb_coeffs(C, c0, c1, c2, c3);
            smf[fo + 0 + z] = c3;
            smf[fo + 2 + z] = c2;
            smf[fo + 4 + z] = c1;
            smf[fo + 6 + z] = c0;
        }
    }
    // L0 sb pairs
    for (int idx = tid; idx < 32; idx += THREADS) {
        int i = idx / 16, q = idx % 16;
        smf[(OFF_L0SB + i * 128 + q * 8) / 4 + 0] = sb0[i * 32 + 2 * q];
        smf[(OFF_L0SB + i * 128 + q * 8) / 4 + 1] = sb0[i * 32 + 2 * q + 1];
    }
    // L2 power-basis: [row 0..15][col]{c3,c2,c1,c0}; row stride 528B; C zero-extended
    for (int idx = tid; idx < 512; idx += THREADS) {
        int r = idx >> 5, col = idx & 31, j = r - 3;
        float C[4];
#pragma unroll
        for (int d = 0; d < 4; d++) {
            int k = j + d;
            C[d] = (k >= 0 && k <= 12) ? sp2[col] * coef2[col * 13 + k] : 0.0f;
        }
        float c0, c1, c2, c3;
        pb_coeffs(C, c0, c1, c2, c3);
        int fo = (OFF_L2 + r * 528 + col * 16) / 4;
        smf[fo + 0] = c3;
        smf[fo + 1] = c2;
        smf[fo + 2] = c1;
        smf[fo + 3] = c0;
    }
    for (int idx = tid; idx < 32; idx += THREADS)
        smf[OFF_L2SB / 4 + idx] = sb2[idx];
    __syncthreads();

    const float bias = dbias[0];
    const uint32_t ABw     = sbase + OFF_ABUF + (uint32_t)wid * 4096u;
    const uint32_t rowbase = ABw + (uint32_t)lane * 128u;
    const uint32_t swzm    = (uint32_t)(lane & 7) << 4;
    const int lrow  = lane & 15;
    const int lcolb = (lane >> 4) * 16;
    const uint32_t rmask = (uint32_t)(lrow & 7) << 4;
    const uint32_t lmA0 = ABw + (uint32_t)lrow * 128u;
    const uint32_t lmA1 = ABw + (uint32_t)(16 + lrow) * 128u;
    const uint4* Bg = reinterpret_cast<const uint4*>(g_bfrag) + lane;

    for (int tile = blockIdx.x; tile < NTILES; tile += gridDim.x) {
        const int pbase = tile * 128 + wid * 32;
        const int p = pbase + lane;

        // ---- layer-0 prep (coords in [0,1) -> j in 0..9) ----
        float2 cc = reinterpret_cast<const float2*>(coords)[p];
        u64 tp[2], bp[2];
        uint32_t Tr[2];
#pragma unroll
        for (int i = 0; i < 2; i++) {
            float x = (i == 0) ? cc.x : cc.y;
            float u = x * 10.0f;
            float fl = floorf(u);
            float t = u - fl;
            int j = (int)fl;
            tp[i] = pack2(t, t);
            float base = x * sigmoidf_(x);
            bp[i] = pack2(base, base);
            Tr[i] = sbase + OFF_L0 + (uint32_t)i * 5280u + (uint32_t)j * 528u;
        }

        // zero + compute h1 (4 outputs, Horner power basis) + scatter, for chunk cidx
        auto do_chunk = [&](int cidx) {
#pragma unroll
            for (int q = 0; q < 8; q++)
                sts128z(rowbase + (((uint32_t)q * 16u) ^ swzm));
            float xv[4];
#pragma unroll
            for (int z = 0; z < 2; z++) {
                uint32_t qi = (uint32_t)(2 * cidx + z);
                uint32_t off = qi * 32u;
                u64 h = 0ull;
#pragma unroll
                for (int i = 0; i < 2; i++) {
                    u64 sbp = lds_b64(sbase + OFF_L0SB + (uint32_t)i * 128u + qi * 8u);
                    fma2(h, bp[i], sbp);
                    u64 c3p, c2p, c1p, c0p;
                    lds128u64(c3p, c2p, Tr[i] + off);
                    lds128u64(c1p, c0p, Tr[i] + off + 16u);
                    u64 s = fma2g(c3p, tp[i], c2p);
                    s = fma2g(s, tp[i], c1p);
                    s = fma2g(s, tp[i], c0p);
                    h = add2(h, s);
                }
                unpack2(h, xv[2 * z], xv[2 * z + 1]);
            }
            // guard-free scatter (invalid taps absorbed by wi guards / dummy slots /
            // slot 0 overwritten by silu)
#pragma unroll
            for (int il = 0; il < 4; il++) {
                float x = xv[il];
                float b0, b1, b2, b3; int j;
                spline_raw(x, b0, b1, b2, b3, j);
                float base = x * sigmoidf_(x);
                uint32_t u01 = h2bits(b0, b1);
                uint32_t u23 = h2bits(b2, b3);
                int s1 = 1 + j;
                int wi = s1 >> 1;
                bool odd = (s1 & 1) != 0;
                uint32_t v1 = odd ? (u01 << 16) : u01;
                uint32_t v2 = odd ? ((u01 >> 16) | (u23 << 16)) : u23;
                uint32_t v3 = odd ? (u23 >> 16) : 0u;
                uint32_t bb = (uint32_t)(32 * il);
                if (wi >= 0) sts32(rowbase + ((bb + 4u * (uint32_t)wi) ^ swzm), v1);
                sts32(rowbase + ((bb + 4u * (uint32_t)(wi + 1)) ^ swzm), v2);
                if (wi <= 5) sts32(rowbase + ((bb + 4u * (uint32_t)(wi + 2)) ^ swzm), v3);
                __half hs = __float2half_rn(base);
                sts16(rowbase + (bb ^ swzm), __half_as_ushort(hs));
            }
        };

        // ---- layer 1: pipelined GEMM D[32x32] = A[32x512] * B ----
        float acc[2][4][4];
#pragma unroll
        for (int mt = 0; mt < 2; mt++)
#pragma unroll
            for (int nt = 0; nt < 4; nt++)
#pragma unroll
                for (int e = 0; e < 4; e++) acc[mt][nt][e] = 0.0f;

        do_chunk(0);

#pragma unroll 1
        for (int c = 0; c < 8; c++) {
            __syncwarp();
            uint32_t afr[4][2][4];
#pragma unroll
            for (int kt = 0; kt < 4; kt++) {
                uint32_t inrow = ((uint32_t)(kt * 32 + lcolb)) ^ rmask;
                ldmatrix_x4(afr[kt][0][0], afr[kt][0][1], afr[kt][0][2], afr[kt][0][3],
                            lmA0 + inrow);
                ldmatrix_x4(afr[kt][1][0], afr[kt][1][1], afr[kt][1][2], afr[kt][1][3],
                            lmA1 + inrow);
            }
            __syncwarp();
            if (c < 7) do_chunk(c + 1);
#pragma unroll
            for (int kt = 0; kt < 4; kt++) {
                int ktg = c * 4 + kt;
#pragma unroll
                for (int np = 0; np < 2; np++) {
                    uint4 bv = __ldg(Bg + (ktg * 2 + np) * 32);
                    mma16816(acc[0][2 * np],     afr[kt][0], bv.x, bv.y);
                    mma16816(acc[1][2 * np],     afr[kt][1], bv.x, bv.y);
                    mma16816(acc[0][2 * np + 1], afr[kt][0], bv.z, bv.w);
                    mma16816(acc[1][2 * np + 1], afr[kt][1], bv.z, bv.w);
                }
            }
        }

        // ---- layer 2 in fragment space (power-basis Horner) ----
        const float* S2 = smf + OFF_L2SB / 4;
        float ps[4] = {0.0f, 0.0f, 0.0f, 0.0f};
#pragma unroll
        for (int mt = 0; mt < 2; mt++)
#pragma unroll
            for (int nt = 0; nt < 4; nt++)
#pragma unroll
                for (int e = 0; e < 4; e++) {
                    float x = acc[mt][nt][e];
                    int col = nt * 8 + 2 * (lane & 3) + (e & 1);
                    float u = x * 10.0f;
                    bool inr = (u >= -3.0f) && (u < 13.0f);
                    float uc = inr ? u : 0.0f;
                    float fl = floorf(uc);
                    float t = uc - fl;
                    int r = (int)fl + 3;       // 0..15 when in range
                    float c3, c2, c1, c0;
                    lds128f(c3, c2, c1, c0,
                            sbase + OFF_L2 + (uint32_t)r * 528u + (uint32_t)col * 16u);
                    float s = fmaf(c3, t, c2);
                    s = fmaf(s, t, c1);
                    s = fmaf(s, t, c0);
                    s = inr ? s : 0.0f;
                    float base = x * sigmoidf_(x);
                    float g = fmaf(S2[col], base, s);
                    ps[mt * 2 + (e >> 1)] += g;
                }
#pragma unroll
        for (int s = 0; s < 4; s++) {
            ps[s] += __shfl_xor_sync(0xffffffffu, ps[s], 1);
            ps[s] += __shfl_xor_sync(0xffffffffu, ps[s], 2);
        }
        if ((lane & 3) == 0) {
#pragma unroll
            for (int s = 0; s < 4; s++) {
                int row = 16 * (s >> 1) + 8 * (s & 1) + (lane >> 2);
                out[pbase + row] = sigmoidf_(ps[s] + bias);
            }
        }
    }
}

extern "C" void kernel_launch(void* const* d_in, const int* in_sizes, int n_in,
                              void* d_out, int out_size)
{
    // order: coords, grid0, coef0, sb0, sp0, grid1, coef1, sb1, sp1, grid2, coef2, sb2, sp2, density_bias
    const float* coords = (const float*)d_in[0];
    const float* coef0  = (const float*)d_in[2];
    const float* sb0    = (const float*)d_in[3];
    const float* sp0    = (const float*)d_in[4];
    const float* coef1  = (const float*)d_in[6];
    const float* sb1    = (const float*)d_in[7];
    const float* sp1    = (const float*)d_in[8];
    const float* coef2  = (const float*)d_in[10];
    const float* sb2    = (const float*)d_in[11];
    const float* sp2    = (const float*)d_in[12];
    const float* dbias  = (const float*)d_in[13];
    float* out = (float*)d_out;

    bfrag_init<<<64, 128>>>(sb1, sp1, coef1);
    cudaFuncSetAttribute(kan_forward, cudaFuncAttributeMaxDynamicSharedMemorySize, SMEM_BYTES);
    kan_forward<<<BLOCKS, THREADS, SMEM_BYTES>>>(coords,
                                                 coef0, sb0, sp0,
                                                 coef2, sb2, sp2,
                                                 dbias, out);
}